// round 7
// baseline (speedup 1.0000x reference)
#include <cuda_runtime.h>
#include <cuda_bf16.h>
#include <cstdint>

// Problem constants
#define BB 32
#define SS 256
#define TT 64
#define EE 256
#define HH 512
#define VV 32000
#define H3 1536

// fc GEMM config (split bf16: K = [Ah|Ah|Al] x [Wh|Wl|Wh])
#define KTOT 3072
#define GBM 128
#define GBN 128
#define GBK 64
#define GLDA 72                 // padded row (bf16 elems)
#define GNC (KTOT / GBK)        // 48
#define GBUF_B (GBM * GLDA * 2) // 18432 bytes
#define FC_SMEM (4 * GBUF_B)    // 73728

// gi GEMM config (K = 768 = [Eh|Eh|El] x [Wh|Wl|Wh])
#define GIK 768
#define GINC (GIK / GBK)        // 12

#define NCTA 128

// ---------------- scratch ----------------
__device__ float g_enc_gi[SS * H3 * BB];
__device__ float g_dec_gie[TT * H3 * BB];
__device__ float g_eo[SS * HH * BB];
__device__ float g_h0[HH * BB];          // never written -> stays zero
__device__ float g_hdec[2][HH * BB];
__device__ float g_ctx[HH * BB];
__device__ float g_scores[SS * BB];
__device__ float g_pred[(TT * BB) * (2 * HH)];
__device__ __nv_bfloat16 g_Wb[(size_t)VV * KTOT];
__device__ __nv_bfloat16 g_Ab[(size_t)(TT * BB) * KTOT];
__device__ __nv_bfloat16 g_Xe[(size_t)(SS * BB) * GIK];
__device__ __nv_bfloat16 g_Xd[(size_t)(TT * BB) * GIK];
__device__ __nv_bfloat16 g_We[(size_t)H3 * GIK];
__device__ __nv_bfloat16 g_Wd[(size_t)H3 * GIK];
__device__ unsigned g_arr[NCTA];   // per-CTA arrival epochs (monotonic)
__device__ unsigned g_gen2;        // release epoch (monotonic)

// ---------------- grid barrier: flag-array arrival, single-word release ----
// Epochs strictly increase across the whole launch sequence (graph-replay safe).
__device__ __forceinline__ unsigned bar_gen0_shared() {
    __shared__ unsigned s_g;
    if (threadIdx.x == 0) s_g = *(volatile unsigned*)&g_gen2;
    __syncthreads();
    return s_g;
}
__device__ __forceinline__ void gsync(unsigned nb, unsigned epoch) {
    __syncthreads();
    if (threadIdx.x == 0) {
        __threadfence();                                 // release data
        ((volatile unsigned*)g_arr)[blockIdx.x] = epoch; // arrive (no atomic)
    }
    if (blockIdx.x == 0) {
        if (threadIdx.x < nb) {
            while ((int)(((volatile unsigned*)g_arr)[threadIdx.x] - epoch) < 0) { }
        }
        __syncthreads();
        if (threadIdx.x == 0) {
            __threadfence();
            *(volatile unsigned*)&g_gen2 = epoch;        // release
        }
    } else {
        if (threadIdx.x == 0) {
            while ((int)(*(volatile unsigned*)&g_gen2 - epoch) < 0) { }
            __threadfence();                             // acquire
        }
    }
    __syncthreads();
}

__device__ __forceinline__ float sigm(float x) { return 1.0f / (1.0f + __expf(-x)); }

__device__ __forceinline__ uint32_t smem_u32(const void* p) {
    uint32_t a;
    asm("{ .reg .u64 t; cvta.to.shared.u64 t, %1; cvt.u32.u64 %0, t; }" : "=r"(a) : "l"(p));
    return a;
}
__device__ __forceinline__ void cpasync16(uint32_t dst, const void* src) {
    asm volatile("cp.async.cg.shared.global [%0], [%1], 16;" :: "r"(dst), "l"(src) : "memory");
}
#define LDSM4(r0, r1, r2, r3, addr) \
    asm volatile("ldmatrix.sync.aligned.m8n8.x4.shared.b16 {%0,%1,%2,%3}, [%4];" \
                 : "=r"(r0), "=r"(r1), "=r"(r2), "=r"(r3) : "r"(addr))
#define MMA16816(c, a, b0, b1) \
    asm volatile("mma.sync.aligned.m16n8k16.row.col.f32.bf16.bf16.f32 " \
                 "{%0,%1,%2,%3}, {%4,%5,%6,%7}, {%8,%9}, {%0,%1,%2,%3};" \
                 : "+f"((c)[0]), "+f"((c)[1]), "+f"((c)[2]), "+f"((c)[3]) \
                 : "r"((a)[0]), "r"((a)[1]), "r"((a)[2]), "r"((a)[3]), "r"(b0), "r"(b1))

// split helpers
__device__ __forceinline__ void split4(float4 v, __nv_bfloat162& hA, __nv_bfloat162& hB,
                                       __nv_bfloat162& lA, __nv_bfloat162& lB) {
    __nv_bfloat16 h0 = __float2bfloat16(v.x), h1 = __float2bfloat16(v.y);
    __nv_bfloat16 h2 = __float2bfloat16(v.z), h3 = __float2bfloat16(v.w);
    __nv_bfloat16 l0 = __float2bfloat16(v.x - __bfloat162float(h0));
    __nv_bfloat16 l1 = __float2bfloat16(v.y - __bfloat162float(h1));
    __nv_bfloat16 l2 = __float2bfloat16(v.z - __bfloat162float(h2));
    __nv_bfloat16 l3 = __float2bfloat16(v.w - __bfloat162float(h3));
    hA = {h0, h1}; hB = {h2, h3}; lA = {l0, l1}; lB = {l2, l3};
}

// ---------------- W split: g_Wb[n] = [hi | lo | hi]
__global__ void convW(const float* __restrict__ W) {
    size_t i = (size_t)blockIdx.x * 1024 + threadIdx.x;
    float4 v = ((const float4*)W)[i];
    size_t n = i >> 8;
    size_t k4 = (i & 255) * 4;
    __nv_bfloat162 hA, hB, lA, lB;
    split4(v, hA, hB, lA, lB);
    __nv_bfloat16* dst = g_Wb + n * KTOT;
    *(__nv_bfloat162*)(dst + k4) = hA;          *(__nv_bfloat162*)(dst + k4 + 2) = hB;
    *(__nv_bfloat162*)(dst + 1024 + k4) = lA;   *(__nv_bfloat162*)(dst + 1024 + k4 + 2) = lB;
    *(__nv_bfloat162*)(dst + 2048 + k4) = hA;   *(__nv_bfloat162*)(dst + 2048 + k4 + 2) = hB;
}

// ---------------- pred split: g_Ab[m] = [hi | hi | lo]
__global__ void convA() {
    size_t i = (size_t)blockIdx.x * 1024 + threadIdx.x;
    float4 v = ((const float4*)g_pred)[i];
    size_t m = i >> 8;
    size_t k4 = (i & 255) * 4;
    __nv_bfloat162 hA, hB, lA, lB;
    split4(v, hA, hB, lA, lB);
    __nv_bfloat16* dst = g_Ab + m * KTOT;
    *(__nv_bfloat162*)(dst + k4) = hA;          *(__nv_bfloat162*)(dst + k4 + 2) = hB;
    *(__nv_bfloat162*)(dst + 1024 + k4) = hA;   *(__nv_bfloat162*)(dst + 1024 + k4 + 2) = hB;
    *(__nv_bfloat162*)(dst + 2048 + k4) = lA;   *(__nv_bfloat162*)(dst + 2048 + k4 + 2) = lB;
}

// ---------------- gather embedding rows + split (globals selected in device code)
__global__ void gatherX(const float* __restrict__ emb, const int* __restrict__ tok,
                        int L, int which) {
    __nv_bfloat16* X = which ? g_Xd : g_Xe;
    int m = blockIdx.x * 8 + (threadIdx.x >> 5);
    int lane = threadIdx.x & 31;
    int t = m >> 5, b = m & 31;
    int tv = tok[b * L + t];
    const float4* er = (const float4*)(emb + (size_t)tv * EE);
    __nv_bfloat16* dst = X + (size_t)m * GIK;
    #pragma unroll
    for (int q = 0; q < 2; q++) {
        float4 v = er[lane * 2 + q];
        int e = lane * 8 + q * 4;
        __nv_bfloat162 hA, hB, lA, lB;
        split4(v, hA, hB, lA, lB);
        *(__nv_bfloat162*)(dst + e) = hA;            *(__nv_bfloat162*)(dst + e + 2) = hB;
        *(__nv_bfloat162*)(dst + 256 + e) = hA;      *(__nv_bfloat162*)(dst + 256 + e + 2) = hB;
        *(__nv_bfloat162*)(dst + 512 + e) = lA;      *(__nv_bfloat162*)(dst + 512 + e + 2) = lB;
    }
}

// ---------------- split Wih rows (first 256 cols)
__global__ void splitWih(const float* __restrict__ W, int stride, int which) {
    __nv_bfloat16* out = which ? g_Wd : g_We;
    int j = blockIdx.x * 8 + (threadIdx.x >> 5);
    int lane = threadIdx.x & 31;
    const float4* wr = (const float4*)(W + (size_t)j * stride);
    __nv_bfloat16* dst = out + (size_t)j * GIK;
    #pragma unroll
    for (int q = 0; q < 2; q++) {
        float4 v = wr[lane * 2 + q];
        int e = lane * 8 + q * 4;
        __nv_bfloat162 hA, hB, lA, lB;
        split4(v, hA, hB, lA, lB);
        *(__nv_bfloat162*)(dst + e) = hA;            *(__nv_bfloat162*)(dst + e + 2) = hB;
        *(__nv_bfloat162*)(dst + 256 + e) = lA;      *(__nv_bfloat162*)(dst + 256 + e + 2) = lB;
        *(__nv_bfloat162*)(dst + 512 + e) = hA;      *(__nv_bfloat162*)(dst + 512 + e + 2) = hB;
    }
}

// ---------------- gi GEMM via HMMA
__global__ void __launch_bounds__(256) gi_mma(const float* __restrict__ bih, int which) {
    extern __shared__ uint8_t dynsmem[];
    uint32_t sA = smem_u32(dynsmem);
    uint32_t sB = sA + 2 * GBUF_B;

    const __nv_bfloat16* A = which ? g_Xd : g_Xe;
    const __nv_bfloat16* Bm = which ? g_Wd : g_We;
    float* outg = which ? g_dec_gie : g_enc_gi;

    int tid = threadIdx.x;
    int wid = tid >> 5, lane = tid & 31;
    int wm = wid & 3, wn = wid >> 2;
    int m0 = blockIdx.x * GBM;
    int n0 = blockIdx.y * GBN;

    const char* Ag = (const char*)(A + (size_t)m0 * GIK);
    const char* Bg = (const char*)(Bm + (size_t)n0 * GIK);
    int lrow = tid >> 3, lu = tid & 7;

    auto load_chunk = [&](int kc, int s) {
        uint32_t sa = sA + s * GBUF_B;
        uint32_t sbm = sB + s * GBUF_B;
        size_t gk = (size_t)kc * GBK * 2;
        #pragma unroll
        for (int it = 0; it < 4; it++) {
            int row = it * 32 + lrow;
            uint32_t doff = (uint32_t)(row * (GLDA * 2) + lu * 16);
            cpasync16(sa + doff, Ag + (size_t)row * (GIK * 2) + gk + lu * 16);
            cpasync16(sbm + doff, Bg + (size_t)row * (GIK * 2) + gk + lu * 16);
        }
        asm volatile("cp.async.commit_group;" ::: "memory");
    };

    float acc[2][8][4];
    #pragma unroll
    for (int a = 0; a < 2; a++)
        #pragma unroll
        for (int b = 0; b < 8; b++)
            #pragma unroll
            for (int c = 0; c < 4; c++) acc[a][b][c] = 0.0f;

    uint32_t aBase = (uint32_t)(((wm * 32 + (lane & 15)) * GLDA + (lane >> 4) * 8) * 2);
    uint32_t bBase = (uint32_t)(((wn * 64 + (lane & 7) + ((lane >> 4) & 1) * 8) * GLDA
                                 + ((lane >> 3) & 1) * 8) * 2);

    load_chunk(0, 0);
    for (int kc = 0; kc < GINC; kc++) {
        int s = kc & 1;
        if (kc + 1 < GINC) {
            load_chunk(kc + 1, s ^ 1);
            asm volatile("cp.async.wait_group 1;" ::: "memory");
        } else {
            asm volatile("cp.async.wait_group 0;" ::: "memory");
        }
        __syncthreads();
        uint32_t sa = sA + s * GBUF_B + aBase;
        uint32_t sbm = sB + s * GBUF_B + bBase;
        #pragma unroll
        for (int ks = 0; ks < 4; ks++) {
            uint32_t koff = (uint32_t)(ks * 16 * 2);
            uint32_t a0[4], a1[4];
            LDSM4(a0[0], a0[1], a0[2], a0[3], sa + koff);
            LDSM4(a1[0], a1[1], a1[2], a1[3], sa + 16 * GLDA * 2 + koff);
            uint32_t bf[16];
            #pragma unroll
            for (int nt = 0; nt < 4; nt++)
                LDSM4(bf[nt * 4 + 0], bf[nt * 4 + 1], bf[nt * 4 + 2], bf[nt * 4 + 3],
                      sbm + nt * 16 * GLDA * 2 + koff);
            #pragma unroll
            for (int j = 0; j < 8; j++) {
                int nt = j >> 1, hf = j & 1;
                MMA16816(acc[0][j], a0, bf[nt * 4 + hf * 2], bf[nt * 4 + hf * 2 + 1]);
                MMA16816(acc[1][j], a1, bf[nt * 4 + hf * 2], bf[nt * 4 + hf * 2 + 1]);
            }
        }
        __syncthreads();
    }

    #pragma unroll
    for (int mt = 0; mt < 2; mt++) {
        #pragma unroll
        for (int half = 0; half < 2; half++) {
            int m = m0 + wm * 32 + mt * 16 + (lane >> 2) + half * 8;
            int t = m >> 5, b = m & 31;
            float* obase = outg + (size_t)t * (H3 * BB) + b;
            #pragma unroll
            for (int j = 0; j < 8; j++) {
                int n = n0 + wn * 64 + j * 8 + (lane & 3) * 2;
                obase[(size_t)n * 32] = acc[mt][j][half * 2 + 0] + __ldg(bih + n);
                obase[(size_t)(n + 1) * 32] = acc[mt][j][half * 2 + 1] + __ldg(bih + n + 1);
            }
        }
    }
}

// ---------------- encoder scan ----------------
__global__ void __launch_bounds__(512) enc_scan(const float* __restrict__ Whh,
                                                const float* __restrict__ bhh) {
    int wid = threadIdx.x >> 5, lane = threadIdx.x & 31;
    int iLocal = wid & 3;
    int kq = wid >> 2;
    int i = blockIdx.x * 4 + iLocal;
    __shared__ float ps[4][3][3][32];
    unsigned gen0 = bar_gen0_shared();

    for (int t = 0; t < SS; t++) {
        const float* hprev = t ? (g_eo + (t - 1) * (HH * BB)) : g_h0;
        float s0 = 0, s1 = 0, s2 = 0;
        {
            const float4* w0 = (const float4*)(Whh + (long)(i) * HH + kq * 128);
            const float4* w1 = (const float4*)(Whh + (long)(HH + i) * HH + kq * 128);
            const float4* w2 = (const float4*)(Whh + (long)(2 * HH + i) * HH + kq * 128);
            const float* hp = hprev + kq * 128 * 32 + lane;
            #pragma unroll 4
            for (int q = 0; q < 32; q++) {
                float h0 = hp[q * 128 + 0];
                float h1 = hp[q * 128 + 32];
                float h2 = hp[q * 128 + 64];
                float h3 = hp[q * 128 + 96];
                float4 w;
                w = w0[q]; s0 += w.x * h0 + w.y * h1 + w.z * h2 + w.w * h3;
                w = w1[q]; s1 += w.x * h0 + w.y * h1 + w.z * h2 + w.w * h3;
                w = w2[q]; s2 += w.x * h0 + w.y * h1 + w.z * h2 + w.w * h3;
            }
        }
        if (kq > 0) {
            ps[iLocal][kq - 1][0][lane] = s0;
            ps[iLocal][kq - 1][1][lane] = s1;
            ps[iLocal][kq - 1][2][lane] = s2;
        }
        __syncthreads();
        if (wid < 4) {
            float rh = s0 + ps[wid][0][0][lane] + ps[wid][1][0][lane] + ps[wid][2][0][lane] + bhh[i];
            float zh = s1 + ps[wid][0][1][lane] + ps[wid][1][1][lane] + ps[wid][2][1][lane] + bhh[HH + i];
            float nh = s2 + ps[wid][0][2][lane] + ps[wid][1][2][lane] + ps[wid][2][2][lane] + bhh[2 * HH + i];
            const float* gi = g_enc_gi + t * (H3 * BB);
            float ir = gi[i * 32 + lane];
            float iz = gi[(HH + i) * 32 + lane];
            float in_ = gi[(2 * HH + i) * 32 + lane];
            float r = sigm(ir + rh);
            float z = sigm(iz + zh);
            float n = tanhf(in_ + r * nh);
            float hv = hprev[i * 32 + lane];
            g_eo[t * (HH * BB) + i * 32 + lane] = (1.0f - z) * n + z * hv;
        }
        gsync(gridDim.x, gen0 + (unsigned)t + 1u);
    }
}

__global__ void copyh() {
    int idx = blockIdx.x * 1024 + threadIdx.x;
    if (idx < HH * BB) g_hdec[0][idx] = g_eo[(SS - 1) * (HH * BB) + idx];
}

// ---------------- decoder scan ----------------
__global__ void __launch_bounds__(512) dec_scan(const float* __restrict__ Whh,
                                                const float* __restrict__ bhh,
                                                const float* __restrict__ Wih,
                                                const int* __restrict__ src) {
    int wid = threadIdx.x >> 5, lane = threadIdx.x & 31;
    __shared__ float psA[2][8][32];
    __shared__ float psC[4][4][32];
    __shared__ float denS[32];
    __shared__ float psD[4][3][6][32];
    unsigned gen0 = bar_gen0_shared();
    unsigned bidx = 0;

    for (int t = 0; t < TT; t++) {
        const float* h = g_hdec[t & 1];
        {
            int s = blockIdx.x * 2 + (wid & 1);
            int kq8 = wid >> 1;
            float acc = 0.0f;
            const float* eo = g_eo + s * (HH * BB) + kq8 * 64 * 32 + lane;
            const float* hp = h + kq8 * 64 * 32 + lane;
            #pragma unroll 8
            for (int k = 0; k < 64; k++) acc += eo[k * 32] * hp[k * 32];
            psA[wid & 1][kq8][lane] = acc;
            __syncthreads();
            if (wid < 2) {
                int ss2 = blockIdx.x * 2 + wid;
                float sc = 0.0f;
                #pragma unroll
                for (int q = 0; q < 8; q++) sc += psA[wid][q][lane];
                int tokv = src[lane * SS + ss2];
                float e = (tokv == 0) ? 0.0f : __expf(sc);
                g_scores[ss2 * 32 + lane] = e;
            }
        }
        gsync(gridDim.x, gen0 + (++bidx));
        {
            int k = blockIdx.x * 4 + (wid & 3);
            int sq = wid >> 2;
            float acc = 0.0f;
            const float* eo = g_eo + sq * 64 * (HH * BB) + k * 32 + lane;
            const float* sce = g_scores + sq * 64 * 32 + lane;
            #pragma unroll 8
            for (int s = 0; s < 64; s++) acc += sce[s * 32] * eo[s * (HH * BB)];
            psC[wid & 3][sq][lane] = acc;
            if (wid == 0) {
                float d = 0.0f;
                const float* sp = g_scores + lane;
                #pragma unroll 8
                for (int s = 0; s < SS; s++) d += sp[s * 32];
                denS[lane] = d;
            }
            __syncthreads();
            if (wid < 4) {
                int kk = blockIdx.x * 4 + wid;
                float c = (psC[wid][0][lane] + psC[wid][1][lane] + psC[wid][2][lane] + psC[wid][3][lane])
                          / denS[lane];
                g_ctx[kk * 32 + lane] = c;
                g_pred[(t * 32 + lane) * (2 * HH) + HH + kk] = c;
            }
        }
        gsync(gridDim.x, gen0 + (++bidx));
        {
            int i = blockIdx.x * 4 + (wid & 3);
            int kq = wid >> 2;
            float a0 = 0, a1 = 0, a2 = 0, c0 = 0, c1 = 0, c2 = 0;
            {
                const float4* wh0 = (const float4*)(Whh + (long)(i) * HH + kq * 128);
                const float4* wh1 = (const float4*)(Whh + (long)(HH + i) * HH + kq * 128);
                const float4* wh2 = (const float4*)(Whh + (long)(2 * HH + i) * HH + kq * 128);
                const float4* wc0 = (const float4*)(Wih + (long)(i) * 768 + EE + kq * 128);
                const float4* wc1 = (const float4*)(Wih + (long)(HH + i) * 768 + EE + kq * 128);
                const float4* wc2 = (const float4*)(Wih + (long)(2 * HH + i) * 768 + EE + kq * 128);
                const float* hp = h + kq * 128 * 32 + lane;
                const float* cp = g_ctx + kq * 128 * 32 + lane;
                #pragma unroll 4
                for (int q = 0; q < 32; q++) {
                    float h0 = hp[q * 128 + 0], h1 = hp[q * 128 + 32];
                    float h2 = hp[q * 128 + 64], h3 = hp[q * 128 + 96];
                    float x0 = cp[q * 128 + 0], x1 = cp[q * 128 + 32];
                    float x2 = cp[q * 128 + 64], x3 = cp[q * 128 + 96];
                    float4 w;
                    w = wh0[q]; a0 += w.x * h0 + w.y * h1 + w.z * h2 + w.w * h3;
                    w = wh1[q]; a1 += w.x * h0 + w.y * h1 + w.z * h2 + w.w * h3;
                    w = wh2[q]; a2 += w.x * h0 + w.y * h1 + w.z * h2 + w.w * h3;
                    w = wc0[q]; c0 += w.x * x0 + w.y * x1 + w.z * x2 + w.w * x3;
                    w = wc1[q]; c1 += w.x * x0 + w.y * x1 + w.z * x2 + w.w * x3;
                    w = wc2[q]; c2 += w.x * x0 + w.y * x1 + w.z * x2 + w.w * x3;
                }
            }
            if (kq > 0) {
                psD[wid & 3][kq - 1][0][lane] = a0;
                psD[wid & 3][kq - 1][1][lane] = a1;
                psD[wid & 3][kq - 1][2][lane] = a2;
                psD[wid & 3][kq - 1][3][lane] = c0;
                psD[wid & 3][kq - 1][4][lane] = c1;
                psD[wid & 3][kq - 1][5][lane] = c2;
            }
            __syncthreads();
            if (wid < 4) {
                float rh = a0, zh = a1, nh = a2, rc = c0, zc = c1, nc = c2;
                #pragma unroll
                for (int kk = 0; kk < 3; kk++) {
                    rh += psD[wid][kk][0][lane];
                    zh += psD[wid][kk][1][lane];
                    nh += psD[wid][kk][2][lane];
                    rc += psD[wid][kk][3][lane];
                    zc += psD[wid][kk][4][lane];
                    nc += psD[wid][kk][5][lane];
                }
                rh += bhh[i]; zh += bhh[HH + i]; nh += bhh[2 * HH + i];
                const float* gie = g_dec_gie + t * (H3 * BB);
                float ir = gie[i * 32 + lane] + rc;
                float iz = gie[(HH + i) * 32 + lane] + zc;
                float in_ = gie[(2 * HH + i) * 32 + lane] + nc;
                float r = sigm(ir + rh);
                float z = sigm(iz + zh);
                float n = tanhf(in_ + r * nh);
                float hold = h[i * 32 + lane];
                float hn = (1.0f - z) * n + z * hold;
                g_hdec[(t + 1) & 1][i * 32 + lane] = hn;
                g_pred[(t * 32 + lane) * (2 * HH) + i] = hn;
            }
        }
        gsync(gridDim.x, gen0 + (++bidx));
    }
}

// ---------------- fc GEMM via mma.sync (HMMA bf16, K=3072) ----------------
__global__ void __launch_bounds__(256) fc_mma(const float* __restrict__ bias,
                                              float* __restrict__ out) {
    extern __shared__ uint8_t dynsmem[];
    uint32_t sA = smem_u32(dynsmem);
    uint32_t sB = sA + 2 * GBUF_B;

    int tid = threadIdx.x;
    int wid = tid >> 5, lane = tid & 31;
    int wm = wid & 3, wn = wid >> 2;
    int m0 = blockIdx.x * GBM;
    int n0 = blockIdx.y * GBN;

    const char* Ag = (const char*)(g_Ab + (size_t)m0 * KTOT);
    const char* Bg = (const char*)(g_Wb + (size_t)n0 * KTOT);

    int lrow = tid >> 3, lu = tid & 7;
    auto load_chunk = [&](int kc, int s) {
        uint32_t sa = sA + s * GBUF_B;
        uint32_t sbm = sB + s * GBUF_B;
        size_t gk = (size_t)kc * GBK * 2;
        #pragma unroll
        for (int it = 0; it < 4; it++) {
            int row = it * 32 + lrow;
            uint32_t doff = (uint32_t)(row * (GLDA * 2) + lu * 16);
            cpasync16(sa + doff, Ag + (size_t)row * (KTOT * 2) + gk + lu * 16);
            cpasync16(sbm + doff, Bg + (size_t)row * (KTOT * 2) + gk + lu * 16);
        }
        asm volatile("cp.async.commit_group;" ::: "memory");
    };

    float acc[2][8][4];
    #pragma unroll
    for (int a = 0; a < 2; a++)
        #pragma unroll
        for (int b = 0; b < 8; b++)
            #pragma unroll
            for (int c = 0; c < 4; c++) acc[a][b][c] = 0.0f;

    uint32_t aBase = (uint32_t)(((wm * 32 + (lane & 15)) * GLDA + (lane >> 4) * 8) * 2);
    uint32_t bBase = (uint32_t)(((wn * 64 + (lane & 7) + ((lane >> 4) & 1) * 8) * GLDA
                                 + ((lane >> 3) & 1) * 8) * 2);

    load_chunk(0, 0);
    for (int kc = 0; kc < GNC; kc++) {
        int s = kc & 1;
        if (kc + 1 < GNC) {
            load_chunk(kc + 1, s ^ 1);
            asm volatile("cp.async.wait_group 1;" ::: "memory");
        } else {
            asm volatile("cp.async.wait_group 0;" ::: "memory");
        }
        __syncthreads();
        uint32_t sa = sA + s * GBUF_B + aBase;
        uint32_t sbm = sB + s * GBUF_B + bBase;
        #pragma unroll
        for (int ks = 0; ks < 4; ks++) {
            uint32_t koff = (uint32_t)(ks * 16 * 2);
            uint32_t a0[4], a1[4];
            LDSM4(a0[0], a0[1], a0[2], a0[3], sa + koff);
            LDSM4(a1[0], a1[1], a1[2], a1[3], sa + 16 * GLDA * 2 + koff);
            uint32_t bf[16];
            #pragma unroll
            for (int nt = 0; nt < 4; nt++)
                LDSM4(bf[nt * 4 + 0], bf[nt * 4 + 1], bf[nt * 4 + 2], bf[nt * 4 + 3],
                      sbm + nt * 16 * GLDA * 2 + koff);
            #pragma unroll
            for (int j = 0; j < 8; j++) {
                int nt = j >> 1, hf = j & 1;
                MMA16816(acc[0][j], a0, bf[nt * 4 + hf * 2], bf[nt * 4 + hf * 2 + 1]);
                MMA16816(acc[1][j], a1, bf[nt * 4 + hf * 2], bf[nt * 4 + hf * 2 + 1]);
            }
        }
        __syncthreads();
    }

    float bv[8][2];
    #pragma unroll
    for (int j = 0; j < 8; j++) {
        int n = n0 + wn * 64 + j * 8 + (lane & 3) * 2;
        bv[j][0] = __ldg(bias + n);
        bv[j][1] = __ldg(bias + n + 1);
    }
    #pragma unroll
    for (int mt = 0; mt < 2; mt++) {
        #pragma unroll
        for (int half = 0; half < 2; half++) {
            int m = m0 + wm * 32 + mt * 16 + (lane >> 2) + half * 8;
            int t = m >> 5, b = m & 31;
            float* orow = out + (size_t)b * (TT * VV) + (size_t)t * VV;
            #pragma unroll
            for (int j = 0; j < 8; j++) {
                int n = n0 + wn * 64 + j * 8 + (lane & 3) * 2;
                float2 v;
                v.x = acc[mt][j][half * 2 + 0] + bv[j][0];
                v.y = acc[mt][j][half * 2 + 1] + bv[j][1];
                *(float2*)(orow + n) = v;
            }
        }
    }
}

// ---------------- launch ----------------
extern "C" void kernel_launch(void* const* d_in, const int* in_sizes, int n_in,
                              void* d_out, int out_size) {
    const int* src = (const int*)d_in[0];
    const int* tgt = (const int*)d_in[2];
    const float* enc_emb = (const float*)d_in[3];
    const float* enc_Wih = (const float*)d_in[4];
    const float* enc_Whh = (const float*)d_in[5];
    const float* enc_bih = (const float*)d_in[6];
    const float* enc_bhh = (const float*)d_in[7];
    const float* dec_emb = (const float*)d_in[8];
    const float* dec_Wih = (const float*)d_in[9];
    const float* dec_Whh = (const float*)d_in[10];
    const float* dec_bih = (const float*)d_in[11];
    const float* dec_bhh = (const float*)d_in[12];
    const float* fc_W = (const float*)d_in[13];
    const float* fc_b = (const float*)d_in[14];
    float* out = (float*)d_out;

    cudaFuncSetAttribute(fc_mma, cudaFuncAttributeMaxDynamicSharedMemorySize, FC_SMEM);
    cudaFuncSetAttribute(gi_mma, cudaFuncAttributeMaxDynamicSharedMemorySize, FC_SMEM);

    // order chosen so enc_scan is the 4th launch (profiled slot)
    gatherX<<<SS * BB / 8, 256>>>(enc_emb, src, SS, 0);              // 1
    splitWih<<<H3 / 8, 256>>>(enc_Wih, EE, 0);                       // 2
    gi_mma<<<dim3(SS * BB / GBM, H3 / GBN), 256, FC_SMEM>>>(enc_bih, 0);  // 3
    enc_scan<<<NCTA, 512>>>(enc_Whh, enc_bhh);                       // 4 <- profiled
    gatherX<<<TT * BB / 8, 256>>>(dec_emb, tgt, TT, 1);              // 5
    splitWih<<<H3 / 8, 256>>>(dec_Wih, EE + HH, 1);                  // 6
    gi_mma<<<dim3(TT * BB / GBM, H3 / GBN), 256, FC_SMEM>>>(dec_bih, 1);  // 7
    copyh<<<16, 1024>>>();                                           // 8
    dec_scan<<<NCTA, 512>>>(dec_Whh, dec_bhh, dec_Wih, src);         // 9
    convA<<<512, 1024>>>();                                          // 10
    convW<<<(VV * 1024) / 4096, 1024>>>(fc_W);                       // 11
    fc_mma<<<dim3(TT * BB / GBM, VV / GBN), 256, FC_SMEM>>>(fc_b, out);   // 12
}

// round 8
// speedup vs baseline: 1.0735x; 1.0735x over previous
#include <cuda_runtime.h>
#include <cuda_bf16.h>
#include <cstdint>

// Problem constants
#define BB 32
#define SS 256
#define TT 64
#define EE 256
#define HH 512
#define VV 32000
#define H3 1536

// shared GEMM fragment config
#define KTOT 3072
#define GBM 128
#define GBK 64
#define GLDA 72                 // padded row (bf16 elems)
#define GBUF_B (GBM * GLDA * 2) // 18432 bytes (128-row buffer)

// gi GEMM (256 thr, 128x128 tile, K=768)
#define GBN 128
#define GIK 768
#define GINC (GIK / GBK)        // 12
#define GI_SMEM (4 * GBUF_B)    // 73728

// fc GEMM (512 thr, 128x256 tile, K=3072)
#define FCBN 256
#define FCBUF_B (FCBN * GLDA * 2)         // 36864
#define GNC (KTOT / GBK)                  // 48
#define FC_SMEM (2 * GBUF_B + 2 * FCBUF_B) // 110592

#define NCTA 128

// ---------------- scratch ----------------
__device__ float g_enc_gi[SS * H3 * BB];
__device__ float g_dec_gie[TT * H3 * BB];
__device__ float g_eo[SS * HH * BB];
__device__ float g_h0[HH * BB];          // never written -> stays zero
__device__ float g_hdec[2][HH * BB];
__device__ float g_ctx[HH * BB];
__device__ float g_scores[SS * BB];
__device__ float g_pred[(TT * BB) * (2 * HH)];
__device__ __nv_bfloat16 g_Wb[(size_t)VV * KTOT];
__device__ __nv_bfloat16 g_Ab[(size_t)(TT * BB) * KTOT];
__device__ __nv_bfloat16 g_Xe[(size_t)(SS * BB) * GIK];
__device__ __nv_bfloat16 g_Xd[(size_t)(TT * BB) * GIK];
__device__ __nv_bfloat16 g_We[(size_t)H3 * GIK];
__device__ __nv_bfloat16 g_Wd[(size_t)H3 * GIK];
__device__ unsigned g_bar_cnt;
__device__ unsigned g_bar_gen;

// ---------------- grid barrier (proven Round-1 implementation) ----------------
__device__ __forceinline__ void grid_sync(unsigned nb) {
    __syncthreads();
    if (threadIdx.x == 0) {
        __threadfence();
        volatile unsigned* genp = &g_bar_gen;
        unsigned gen = *genp;
        if (atomicAdd(&g_bar_cnt, 1u) == nb - 1u) {
            g_bar_cnt = 0;
            __threadfence();
            *genp = gen + 1u;
        } else {
            while (*genp == gen) { }
            __threadfence();
        }
    }
    __syncthreads();
}

__device__ __forceinline__ float sigm(float x) { return 1.0f / (1.0f + __expf(-x)); }

__device__ __forceinline__ uint32_t smem_u32(const void* p) {
    uint32_t a;
    asm("{ .reg .u64 t; cvta.to.shared.u64 t, %1; cvt.u32.u64 %0, t; }" : "=r"(a) : "l"(p));
    return a;
}
__device__ __forceinline__ void cpasync16(uint32_t dst, const void* src) {
    asm volatile("cp.async.cg.shared.global [%0], [%1], 16;" :: "r"(dst), "l"(src) : "memory");
}
#define LDSM4(r0, r1, r2, r3, addr) \
    asm volatile("ldmatrix.sync.aligned.m8n8.x4.shared.b16 {%0,%1,%2,%3}, [%4];" \
                 : "=r"(r0), "=r"(r1), "=r"(r2), "=r"(r3) : "r"(addr))
#define MMA16816(c, a, b0, b1) \
    asm volatile("mma.sync.aligned.m16n8k16.row.col.f32.bf16.bf16.f32 " \
                 "{%0,%1,%2,%3}, {%4,%5,%6,%7}, {%8,%9}, {%0,%1,%2,%3};" \
                 : "+f"((c)[0]), "+f"((c)[1]), "+f"((c)[2]), "+f"((c)[3]) \
                 : "r"((a)[0]), "r"((a)[1]), "r"((a)[2]), "r"((a)[3]), "r"(b0), "r"(b1))

// split helpers
__device__ __forceinline__ void split4(float4 v, __nv_bfloat162& hA, __nv_bfloat162& hB,
                                       __nv_bfloat162& lA, __nv_bfloat162& lB) {
    __nv_bfloat16 h0 = __float2bfloat16(v.x), h1 = __float2bfloat16(v.y);
    __nv_bfloat16 h2 = __float2bfloat16(v.z), h3 = __float2bfloat16(v.w);
    __nv_bfloat16 l0 = __float2bfloat16(v.x - __bfloat162float(h0));
    __nv_bfloat16 l1 = __float2bfloat16(v.y - __bfloat162float(h1));
    __nv_bfloat16 l2 = __float2bfloat16(v.z - __bfloat162float(h2));
    __nv_bfloat16 l3 = __float2bfloat16(v.w - __bfloat162float(h3));
    hA = {h0, h1}; hB = {h2, h3}; lA = {l0, l1}; lB = {l2, l3};
}

// ---------------- W split: g_Wb[n] = [hi | lo | hi]
__global__ void convW(const float* __restrict__ W) {
    size_t i = (size_t)blockIdx.x * 1024 + threadIdx.x;
    float4 v = ((const float4*)W)[i];
    size_t n = i >> 8;
    size_t k4 = (i & 255) * 4;
    __nv_bfloat162 hA, hB, lA, lB;
    split4(v, hA, hB, lA, lB);
    __nv_bfloat16* dst = g_Wb + n * KTOT;
    *(__nv_bfloat162*)(dst + k4) = hA;          *(__nv_bfloat162*)(dst + k4 + 2) = hB;
    *(__nv_bfloat162*)(dst + 1024 + k4) = lA;   *(__nv_bfloat162*)(dst + 1024 + k4 + 2) = lB;
    *(__nv_bfloat162*)(dst + 2048 + k4) = hA;   *(__nv_bfloat162*)(dst + 2048 + k4 + 2) = hB;
}

// ---------------- pred split: g_Ab[m] = [hi | hi | lo]
__global__ void convA() {
    size_t i = (size_t)blockIdx.x * 1024 + threadIdx.x;
    float4 v = ((const float4*)g_pred)[i];
    size_t m = i >> 8;
    size_t k4 = (i & 255) * 4;
    __nv_bfloat162 hA, hB, lA, lB;
    split4(v, hA, hB, lA, lB);
    __nv_bfloat16* dst = g_Ab + m * KTOT;
    *(__nv_bfloat162*)(dst + k4) = hA;          *(__nv_bfloat162*)(dst + k4 + 2) = hB;
    *(__nv_bfloat162*)(dst + 1024 + k4) = hA;   *(__nv_bfloat162*)(dst + 1024 + k4 + 2) = hB;
    *(__nv_bfloat162*)(dst + 2048 + k4) = lA;   *(__nv_bfloat162*)(dst + 2048 + k4 + 2) = lB;
}

// ---------------- gather embedding rows + split
__global__ void gatherX(const float* __restrict__ emb, const int* __restrict__ tok,
                        int L, int which) {
    __nv_bfloat16* X = which ? g_Xd : g_Xe;
    int m = blockIdx.x * 8 + (threadIdx.x >> 5);
    int lane = threadIdx.x & 31;
    int t = m >> 5, b = m & 31;
    int tv = tok[b * L + t];
    const float4* er = (const float4*)(emb + (size_t)tv * EE);
    __nv_bfloat16* dst = X + (size_t)m * GIK;
    #pragma unroll
    for (int q = 0; q < 2; q++) {
        float4 v = er[lane * 2 + q];
        int e = lane * 8 + q * 4;
        __nv_bfloat162 hA, hB, lA, lB;
        split4(v, hA, hB, lA, lB);
        *(__nv_bfloat162*)(dst + e) = hA;            *(__nv_bfloat162*)(dst + e + 2) = hB;
        *(__nv_bfloat162*)(dst + 256 + e) = hA;      *(__nv_bfloat162*)(dst + 256 + e + 2) = hB;
        *(__nv_bfloat162*)(dst + 512 + e) = lA;      *(__nv_bfloat162*)(dst + 512 + e + 2) = lB;
    }
}

// ---------------- split Wih rows (first 256 cols)
__global__ void splitWih(const float* __restrict__ W, int stride, int which) {
    __nv_bfloat16* out = which ? g_Wd : g_We;
    int j = blockIdx.x * 8 + (threadIdx.x >> 5);
    int lane = threadIdx.x & 31;
    const float4* wr = (const float4*)(W + (size_t)j * stride);
    __nv_bfloat16* dst = out + (size_t)j * GIK;
    #pragma unroll
    for (int q = 0; q < 2; q++) {
        float4 v = wr[lane * 2 + q];
        int e = lane * 8 + q * 4;
        __nv_bfloat162 hA, hB, lA, lB;
        split4(v, hA, hB, lA, lB);
        *(__nv_bfloat162*)(dst + e) = hA;            *(__nv_bfloat162*)(dst + e + 2) = hB;
        *(__nv_bfloat162*)(dst + 256 + e) = lA;      *(__nv_bfloat162*)(dst + 256 + e + 2) = lB;
        *(__nv_bfloat162*)(dst + 512 + e) = hA;      *(__nv_bfloat162*)(dst + 512 + e + 2) = hB;
    }
}

// ---------------- gi GEMM via HMMA (256 thr, 128x128)
__global__ void __launch_bounds__(256) gi_mma(const float* __restrict__ bih, int which) {
    extern __shared__ uint8_t dynsmem[];
    uint32_t sA = smem_u32(dynsmem);
    uint32_t sB = sA + 2 * GBUF_B;

    const __nv_bfloat16* A = which ? g_Xd : g_Xe;
    const __nv_bfloat16* Bm = which ? g_Wd : g_We;
    float* outg = which ? g_dec_gie : g_enc_gi;

    int tid = threadIdx.x;
    int wid = tid >> 5, lane = tid & 31;
    int wm = wid & 3, wn = wid >> 2;
    int m0 = blockIdx.x * GBM;
    int n0 = blockIdx.y * GBN;

    const char* Ag = (const char*)(A + (size_t)m0 * GIK);
    const char* Bg = (const char*)(Bm + (size_t)n0 * GIK);
    int lrow = tid >> 3, lu = tid & 7;

    auto load_chunk = [&](int kc, int s) {
        uint32_t sa = sA + s * GBUF_B;
        uint32_t sbm = sB + s * GBUF_B;
        size_t gk = (size_t)kc * GBK * 2;
        #pragma unroll
        for (int it = 0; it < 4; it++) {
            int row = it * 32 + lrow;
            uint32_t doff = (uint32_t)(row * (GLDA * 2) + lu * 16);
            cpasync16(sa + doff, Ag + (size_t)row * (GIK * 2) + gk + lu * 16);
            cpasync16(sbm + doff, Bg + (size_t)row * (GIK * 2) + gk + lu * 16);
        }
        asm volatile("cp.async.commit_group;" ::: "memory");
    };

    float acc[2][8][4];
    #pragma unroll
    for (int a = 0; a < 2; a++)
        #pragma unroll
        for (int b = 0; b < 8; b++)
            #pragma unroll
            for (int c = 0; c < 4; c++) acc[a][b][c] = 0.0f;

    uint32_t aBase = (uint32_t)(((wm * 32 + (lane & 15)) * GLDA + (lane >> 4) * 8) * 2);
    uint32_t bBase = (uint32_t)(((wn * 64 + (lane & 7) + ((lane >> 4) & 1) * 8) * GLDA
                                 + ((lane >> 3) & 1) * 8) * 2);

    load_chunk(0, 0);
    for (int kc = 0; kc < GINC; kc++) {
        int s = kc & 1;
        if (kc + 1 < GINC) {
            load_chunk(kc + 1, s ^ 1);
            asm volatile("cp.async.wait_group 1;" ::: "memory");
        } else {
            asm volatile("cp.async.wait_group 0;" ::: "memory");
        }
        __syncthreads();
        uint32_t sa = sA + s * GBUF_B + aBase;
        uint32_t sbm = sB + s * GBUF_B + bBase;
        #pragma unroll
        for (int ks = 0; ks < 4; ks++) {
            uint32_t koff = (uint32_t)(ks * 16 * 2);
            uint32_t a0[4], a1[4];
            LDSM4(a0[0], a0[1], a0[2], a0[3], sa + koff);
            LDSM4(a1[0], a1[1], a1[2], a1[3], sa + 16 * GLDA * 2 + koff);
            uint32_t bf[16];
            #pragma unroll
            for (int nt = 0; nt < 4; nt++)
                LDSM4(bf[nt * 4 + 0], bf[nt * 4 + 1], bf[nt * 4 + 2], bf[nt * 4 + 3],
                      sbm + nt * 16 * GLDA * 2 + koff);
            #pragma unroll
            for (int j = 0; j < 8; j++) {
                int nt = j >> 1, hf = j & 1;
                MMA16816(acc[0][j], a0, bf[nt * 4 + hf * 2], bf[nt * 4 + hf * 2 + 1]);
                MMA16816(acc[1][j], a1, bf[nt * 4 + hf * 2], bf[nt * 4 + hf * 2 + 1]);
            }
        }
        __syncthreads();
    }

    #pragma unroll
    for (int mt = 0; mt < 2; mt++) {
        #pragma unroll
        for (int half = 0; half < 2; half++) {
            int m = m0 + wm * 32 + mt * 16 + (lane >> 2) + half * 8;
            int t = m >> 5, b = m & 31;
            float* obase = outg + (size_t)t * (H3 * BB) + b;
            #pragma unroll
            for (int j = 0; j < 8; j++) {
                int n = n0 + wn * 64 + j * 8 + (lane & 3) * 2;
                obase[(size_t)n * 32] = acc[mt][j][half * 2 + 0] + __ldg(bih + n);
                obase[(size_t)(n + 1) * 32] = acc[mt][j][half * 2 + 1] + __ldg(bih + n + 1);
            }
        }
    }
}

// ---------------- encoder scan ----------------
__global__ void __launch_bounds__(512) enc_scan(const float* __restrict__ Whh,
                                                const float* __restrict__ bhh) {
    int wid = threadIdx.x >> 5, lane = threadIdx.x & 31;
    int iLocal = wid & 3;
    int kq = wid >> 2;
    int i = blockIdx.x * 4 + iLocal;
    __shared__ float ps[4][3][3][32];

    for (int t = 0; t < SS; t++) {
        const float* hprev = t ? (g_eo + (t - 1) * (HH * BB)) : g_h0;
        float s0 = 0, s1 = 0, s2 = 0;
        {
            const float4* w0 = (const float4*)(Whh + (long)(i) * HH + kq * 128);
            const float4* w1 = (const float4*)(Whh + (long)(HH + i) * HH + kq * 128);
            const float4* w2 = (const float4*)(Whh + (long)(2 * HH + i) * HH + kq * 128);
            const float* hp = hprev + kq * 128 * 32 + lane;
            #pragma unroll 4
            for (int q = 0; q < 32; q++) {
                float h0 = hp[q * 128 + 0];
                float h1 = hp[q * 128 + 32];
                float h2 = hp[q * 128 + 64];
                float h3 = hp[q * 128 + 96];
                float4 w;
                w = w0[q]; s0 += w.x * h0 + w.y * h1 + w.z * h2 + w.w * h3;
                w = w1[q]; s1 += w.x * h0 + w.y * h1 + w.z * h2 + w.w * h3;
                w = w2[q]; s2 += w.x * h0 + w.y * h1 + w.z * h2 + w.w * h3;
            }
        }
        if (kq > 0) {
            ps[iLocal][kq - 1][0][lane] = s0;
            ps[iLocal][kq - 1][1][lane] = s1;
            ps[iLocal][kq - 1][2][lane] = s2;
        }
        __syncthreads();
        if (wid < 4) {
            float rh = s0 + ps[wid][0][0][lane] + ps[wid][1][0][lane] + ps[wid][2][0][lane] + bhh[i];
            float zh = s1 + ps[wid][0][1][lane] + ps[wid][1][1][lane] + ps[wid][2][1][lane] + bhh[HH + i];
            float nh = s2 + ps[wid][0][2][lane] + ps[wid][1][2][lane] + ps[wid][2][2][lane] + bhh[2 * HH + i];
            const float* gi = g_enc_gi + t * (H3 * BB);
            float ir = gi[i * 32 + lane];
            float iz = gi[(HH + i) * 32 + lane];
            float in_ = gi[(2 * HH + i) * 32 + lane];
            float r = sigm(ir + rh);
            float z = sigm(iz + zh);
            float n = tanhf(in_ + r * nh);
            float hv = hprev[i * 32 + lane];
            g_eo[t * (HH * BB) + i * 32 + lane] = (1.0f - z) * n + z * hv;
        }
        grid_sync(gridDim.x);
    }
}

__global__ void copyh() {
    int idx = blockIdx.x * 1024 + threadIdx.x;
    if (idx < HH * BB) g_hdec[0][idx] = g_eo[(SS - 1) * (HH * BB) + idx];
}

// ---------------- decoder scan ----------------
__global__ void __launch_bounds__(512) dec_scan(const float* __restrict__ Whh,
                                                const float* __restrict__ bhh,
                                                const float* __restrict__ Wih,
                                                const int* __restrict__ src) {
    int wid = threadIdx.x >> 5, lane = threadIdx.x & 31;
    __shared__ float psA[2][8][32];
    __shared__ float psC[4][4][32];
    __shared__ float denS[32];
    __shared__ float psD[4][3][6][32];

    for (int t = 0; t < TT; t++) {
        const float* h = g_hdec[t & 1];
        {
            int s = blockIdx.x * 2 + (wid & 1);
            int kq8 = wid >> 1;
            float acc = 0.0f;
            const float* eo = g_eo + s * (HH * BB) + kq8 * 64 * 32 + lane;
            const float* hp = h + kq8 * 64 * 32 + lane;
            #pragma unroll 8
            for (int k = 0; k < 64; k++) acc += eo[k * 32] * hp[k * 32];
            psA[wid & 1][kq8][lane] = acc;
            __syncthreads();
            if (wid < 2) {
                int ss2 = blockIdx.x * 2 + wid;
                float sc = 0.0f;
                #pragma unroll
                for (int q = 0; q < 8; q++) sc += psA[wid][q][lane];
                int tokv = src[lane * SS + ss2];
                float e = (tokv == 0) ? 0.0f : __expf(sc);
                g_scores[ss2 * 32 + lane] = e;
            }
        }
        grid_sync(gridDim.x);
        {
            int k = blockIdx.x * 4 + (wid & 3);
            int sq = wid >> 2;
            float acc = 0.0f;
            const float* eo = g_eo + sq * 64 * (HH * BB) + k * 32 + lane;
            const float* sce = g_scores + sq * 64 * 32 + lane;
            #pragma unroll 8
            for (int s = 0; s < 64; s++) acc += sce[s * 32] * eo[s * (HH * BB)];
            psC[wid & 3][sq][lane] = acc;
            if (wid == 0) {
                float d = 0.0f;
                const float* sp = g_scores + lane;
                #pragma unroll 8
                for (int s = 0; s < SS; s++) d += sp[s * 32];
                denS[lane] = d;
            }
            __syncthreads();
            if (wid < 4) {
                int kk = blockIdx.x * 4 + wid;
                float c = (psC[wid][0][lane] + psC[wid][1][lane] + psC[wid][2][lane] + psC[wid][3][lane])
                          / denS[lane];
                g_ctx[kk * 32 + lane] = c;
                g_pred[(t * 32 + lane) * (2 * HH) + HH + kk] = c;
            }
        }
        grid_sync(gridDim.x);
        {
            int i = blockIdx.x * 4 + (wid & 3);
            int kq = wid >> 2;
            float a0 = 0, a1 = 0, a2 = 0, c0 = 0, c1 = 0, c2 = 0;
            {
                const float4* wh0 = (const float4*)(Whh + (long)(i) * HH + kq * 128);
                const float4* wh1 = (const float4*)(Whh + (long)(HH + i) * HH + kq * 128);
                const float4* wh2 = (const float4*)(Whh + (long)(2 * HH + i) * HH + kq * 128);
                const float4* wc0 = (const float4*)(Wih + (long)(i) * 768 + EE + kq * 128);
                const float4* wc1 = (const float4*)(Wih + (long)(HH + i) * 768 + EE + kq * 128);
                const float4* wc2 = (const float4*)(Wih + (long)(2 * HH + i) * 768 + EE + kq * 128);
                const float* hp = h + kq * 128 * 32 + lane;
                const float* cp = g_ctx + kq * 128 * 32 + lane;
                #pragma unroll 4
                for (int q = 0; q < 32; q++) {
                    float h0 = hp[q * 128 + 0], h1 = hp[q * 128 + 32];
                    float h2 = hp[q * 128 + 64], h3 = hp[q * 128 + 96];
                    float x0 = cp[q * 128 + 0], x1 = cp[q * 128 + 32];
                    float x2 = cp[q * 128 + 64], x3 = cp[q * 128 + 96];
                    float4 w;
                    w = wh0[q]; a0 += w.x * h0 + w.y * h1 + w.z * h2 + w.w * h3;
                    w = wh1[q]; a1 += w.x * h0 + w.y * h1 + w.z * h2 + w.w * h3;
                    w = wh2[q]; a2 += w.x * h0 + w.y * h1 + w.z * h2 + w.w * h3;
                    w = wc0[q]; c0 += w.x * x0 + w.y * x1 + w.z * x2 + w.w * x3;
                    w = wc1[q]; c1 += w.x * x0 + w.y * x1 + w.z * x2 + w.w * x3;
                    w = wc2[q]; c2 += w.x * x0 + w.y * x1 + w.z * x2 + w.w * x3;
                }
            }
            if (kq > 0) {
                psD[wid & 3][kq - 1][0][lane] = a0;
                psD[wid & 3][kq - 1][1][lane] = a1;
                psD[wid & 3][kq - 1][2][lane] = a2;
                psD[wid & 3][kq - 1][3][lane] = c0;
                psD[wid & 3][kq - 1][4][lane] = c1;
                psD[wid & 3][kq - 1][5][lane] = c2;
            }
            __syncthreads();
            if (wid < 4) {
                float rh = a0, zh = a1, nh = a2, rc = c0, zc = c1, nc = c2;
                #pragma unroll
                for (int kk = 0; kk < 3; kk++) {
                    rh += psD[wid][kk][0][lane];
                    zh += psD[wid][kk][1][lane];
                    nh += psD[wid][kk][2][lane];
                    rc += psD[wid][kk][3][lane];
                    zc += psD[wid][kk][4][lane];
                    nc += psD[wid][kk][5][lane];
                }
                rh += bhh[i]; zh += bhh[HH + i]; nh += bhh[2 * HH + i];
                const float* gie = g_dec_gie + t * (H3 * BB);
                float ir = gie[i * 32 + lane] + rc;
                float iz = gie[(HH + i) * 32 + lane] + zc;
                float in_ = gie[(2 * HH + i) * 32 + lane] + nc;
                float r = sigm(ir + rh);
                float z = sigm(iz + zh);
                float n = tanhf(in_ + r * nh);
                float hold = h[i * 32 + lane];
                float hn = (1.0f - z) * n + z * hold;
                g_hdec[(t + 1) & 1][i * 32 + lane] = hn;
                g_pred[(t * 32 + lane) * (2 * HH) + i] = hn;
            }
        }
        grid_sync(gridDim.x);
    }
}

// ---------------- fc GEMM via mma.sync: 512 thr, 128x256 tile, K=3072 ----------------
__global__ void __launch_bounds__(512) fc_mma(const float* __restrict__ bias,
                                              float* __restrict__ out) {
    extern __shared__ uint8_t dynsmem[];
    uint32_t sA = smem_u32(dynsmem);           // 2 x 18432
    uint32_t sB = sA + 2 * GBUF_B;             // 2 x 36864

    int tid = threadIdx.x;
    int wid = tid >> 5, lane = tid & 31;
    int wm = wid & 3, wn = wid >> 2;           // wm 0..3, wn 0..3
    int m0 = blockIdx.x * GBM;
    int n0 = blockIdx.y * FCBN;

    const char* Ag = (const char*)(g_Ab + (size_t)m0 * KTOT);
    const char* Bg = (const char*)(g_Wb + (size_t)n0 * KTOT);

    int lrow = tid >> 3, lu = tid & 7;         // lrow 0..63
    auto load_chunk = [&](int kc, int s) {
        uint32_t sa = sA + s * GBUF_B;
        uint32_t sbm = sB + s * FCBUF_B;
        size_t gk = (size_t)kc * GBK * 2;
        #pragma unroll
        for (int it = 0; it < 2; it++) {       // A: 128 rows
            int row = it * 64 + lrow;
            uint32_t doff = (uint32_t)(row * (GLDA * 2) + lu * 16);
            cpasync16(sa + doff, Ag + (size_t)row * (KTOT * 2) + gk + lu * 16);
        }
        #pragma unroll
        for (int it = 0; it < 4; it++) {       // B: 256 rows
            int row = it * 64 + lrow;
            uint32_t doff = (uint32_t)(row * (GLDA * 2) + lu * 16);
            cpasync16(sbm + doff, Bg + (size_t)row * (KTOT * 2) + gk + lu * 16);
        }
        asm volatile("cp.async.commit_group;" ::: "memory");
    };

    float acc[2][8][4];
    #pragma unroll
    for (int a = 0; a < 2; a++)
        #pragma unroll
        for (int b = 0; b < 8; b++)
            #pragma unroll
            for (int c = 0; c < 4; c++) acc[a][b][c] = 0.0f;

    uint32_t aBase = (uint32_t)(((wm * 32 + (lane & 15)) * GLDA + (lane >> 4) * 8) * 2);
    uint32_t bBase = (uint32_t)(((wn * 64 + (lane & 7) + ((lane >> 4) & 1) * 8) * GLDA
                                 + ((lane >> 3) & 1) * 8) * 2);

    load_chunk(0, 0);
    for (int kc = 0; kc < GNC; kc++) {
        int s = kc & 1;
        if (kc + 1 < GNC) {
            load_chunk(kc + 1, s ^ 1);
            asm volatile("cp.async.wait_group 1;" ::: "memory");
        } else {
            asm volatile("cp.async.wait_group 0;" ::: "memory");
        }
        __syncthreads();
        uint32_t sa = sA + s * GBUF_B + aBase;
        uint32_t sbm = sB + s * FCBUF_B + bBase;
        #pragma unroll
        for (int ks = 0; ks < 4; ks++) {
            uint32_t koff = (uint32_t)(ks * 16 * 2);
            uint32_t a0[4], a1[4];
            LDSM4(a0[0], a0[1], a0[2], a0[3], sa + koff);
            LDSM4(a1[0], a1[1], a1[2], a1[3], sa + 16 * GLDA * 2 + koff);
            uint32_t bf[16];
            #pragma unroll
            for (int nt = 0; nt < 4; nt++)
                LDSM4(bf[nt * 4 + 0], bf[nt * 4 + 1], bf[nt * 4 + 2], bf[nt * 4 + 3],
                      sbm + nt * 16 * GLDA * 2 + koff);
            #pragma unroll
            for (int j = 0; j < 8; j++) {
                int nt = j >> 1, hf = j & 1;
                MMA16816(acc[0][j], a0, bf[nt * 4 + hf * 2], bf[nt * 4 + hf * 2 + 1]);
                MMA16816(acc[1][j], a1, bf[nt * 4 + hf * 2], bf[nt * 4 + hf * 2 + 1]);
            }
        }
        __syncthreads();
    }

    float bv[8][2];
    #pragma unroll
    for (int j = 0; j < 8; j++) {
        int n = n0 + wn * 64 + j * 8 + (lane & 3) * 2;
        bv[j][0] = __ldg(bias + n);
        bv[j][1] = __ldg(bias + n + 1);
    }
    #pragma unroll
    for (int mt = 0; mt < 2; mt++) {
        #pragma unroll
        for (int half = 0; half < 2; half++) {
            int m = m0 + wm * 32 + mt * 16 + (lane >> 2) + half * 8;
            int t = m >> 5, b = m & 31;
            float* orow = out + (size_t)b * (TT * VV) + (size_t)t * VV;
            #pragma unroll
            for (int j = 0; j < 8; j++) {
                int n = n0 + wn * 64 + j * 8 + (lane & 3) * 2;
                float2 v;
                v.x = acc[mt][j][half * 2 + 0] + bv[j][0];
                v.y = acc[mt][j][half * 2 + 1] + bv[j][1];
                *(float2*)(orow + n) = v;
            }
        }
    }
}

// ---------------- launch ----------------
extern "C" void kernel_launch(void* const* d_in, const int* in_sizes, int n_in,
                              void* d_out, int out_size) {
    const int* src = (const int*)d_in[0];
    const int* tgt = (const int*)d_in[2];
    const float* enc_emb = (const float*)d_in[3];
    const float* enc_Wih = (const float*)d_in[4];
    const float* enc_Whh = (const float*)d_in[5];
    const float* enc_bih = (const float*)d_in[6];
    const float* enc_bhh = (const float*)d_in[7];
    const float* dec_emb = (const float*)d_in[8];
    const float* dec_Wih = (const float*)d_in[9];
    const float* dec_Whh = (const float*)d_in[10];
    const float* dec_bih = (const float*)d_in[11];
    const float* dec_bhh = (const float*)d_in[12];
    const float* fc_W = (const float*)d_in[13];
    const float* fc_b = (const float*)d_in[14];
    float* out = (float*)d_out;

    cudaFuncSetAttribute(fc_mma, cudaFuncAttributeMaxDynamicSharedMemorySize, FC_SMEM);
    cudaFuncSetAttribute(gi_mma, cudaFuncAttributeMaxDynamicSharedMemorySize, GI_SMEM);

    gatherX<<<SS * BB / 8, 256>>>(enc_emb, src, SS, 0);
    splitWih<<<H3 / 8, 256>>>(enc_Wih, EE, 0);
    gi_mma<<<dim3(SS * BB / GBM, H3 / GBN), 256, GI_SMEM>>>(enc_bih, 0);
    enc_scan<<<NCTA, 512>>>(enc_Whh, enc_bhh);
    gatherX<<<TT * BB / 8, 256>>>(dec_emb, tgt, TT, 1);
    splitWih<<<H3 / 8, 256>>>(dec_Wih, EE + HH, 1);
    gi_mma<<<dim3(TT * BB / GBM, H3 / GBN), 256, GI_SMEM>>>(dec_bih, 1);
    copyh<<<16, 1024>>>();
    dec_scan<<<NCTA, 512>>>(dec_Whh, dec_bhh, dec_Wih, src);
    convA<<<512, 1024>>>();
    convW<<<(VV * 1024) / 4096, 1024>>>(fc_W);
    fc_mma<<<dim3(TT * BB / GBM, VV / FCBN), 512, FC_SMEM>>>(fc_b, out);
}

// round 9
// speedup vs baseline: 1.0746x; 1.0010x over previous
#include <cuda_runtime.h>
#include <cuda_bf16.h>
#include <cstdint>

// Problem constants
#define BB 32
#define SS 256
#define TT 64
#define EE 256
#define HH 512
#define VV 32000
#define H3 1536

// shared GEMM fragment config
#define KTOT 3072
#define GBM 128
#define GBK 64
#define GLDA 72                 // padded row (bf16 elems)
#define GBUF_B (GBM * GLDA * 2) // 18432 bytes (128-row buffer)

// gi GEMM (256 thr, 128x128 tile, K=768)
#define GBN 128
#define GIK 768
#define GINC (GIK / GBK)        // 12
#define GI_SMEM (4 * GBUF_B)    // 73728

// fc GEMM (512 thr, 128x256 tile, K=3072)
#define FCBN 256
#define FCBUF_B (FCBN * GLDA * 2)         // 36864
#define GNC (KTOT / GBK)                  // 48
#define FC_SMEM (2 * GBUF_B + 2 * FCBUF_B) // 110592

#define NCTA 128

// ---------------- scratch ----------------
__device__ float g_enc_gi[SS * H3 * BB];
__device__ float g_dec_gie[TT * H3 * BB];
__device__ float g_eo[SS * HH * BB];
__device__ float g_h0[HH * BB];          // never written -> stays zero
__device__ float g_hdec[2][HH * BB];
__device__ float g_ctx[HH * BB];
__device__ float g_scores[SS * BB];
__device__ float g_pred[(TT * BB) * (2 * HH)];
__device__ __nv_bfloat16 g_Wb[(size_t)VV * KTOT];
__device__ __nv_bfloat16 g_Ab[(size_t)(TT * BB) * KTOT];
__device__ __nv_bfloat16 g_Xe[(size_t)(SS * BB) * GIK];
__device__ __nv_bfloat16 g_Xd[(size_t)(TT * BB) * GIK];
__device__ __nv_bfloat16 g_We[(size_t)H3 * GIK];
__device__ __nv_bfloat16 g_Wd[(size_t)H3 * GIK];
__device__ unsigned g_bar_cnt;
__device__ unsigned g_bar_gen;

// ---------------- grid barrier (proven Round-1 implementation) ----------------
__device__ __forceinline__ void grid_sync(unsigned nb) {
    __syncthreads();
    if (threadIdx.x == 0) {
        __threadfence();
        volatile unsigned* genp = &g_bar_gen;
        unsigned gen = *genp;
        if (atomicAdd(&g_bar_cnt, 1u) == nb - 1u) {
            g_bar_cnt = 0;
            __threadfence();
            *genp = gen + 1u;
        } else {
            while (*genp == gen) { }
            __threadfence();
        }
    }
    __syncthreads();
}

__device__ __forceinline__ float sigm(float x) { return 1.0f / (1.0f + __expf(-x)); }

__device__ __forceinline__ uint32_t smem_u32(const void* p) {
    uint32_t a;
    asm("{ .reg .u64 t; cvta.to.shared.u64 t, %1; cvt.u32.u64 %0, t; }" : "=r"(a) : "l"(p));
    return a;
}
__device__ __forceinline__ void cpasync16(uint32_t dst, const void* src) {
    asm volatile("cp.async.cg.shared.global [%0], [%1], 16;" :: "r"(dst), "l"(src) : "memory");
}
#define LDSM4(r0, r1, r2, r3, addr) \
    asm volatile("ldmatrix.sync.aligned.m8n8.x4.shared.b16 {%0,%1,%2,%3}, [%4];" \
                 : "=r"(r0), "=r"(r1), "=r"(r2), "=r"(r3) : "r"(addr))
#define MMA16816(c, a, b0, b1) \
    asm volatile("mma.sync.aligned.m16n8k16.row.col.f32.bf16.bf16.f32 " \
                 "{%0,%1,%2,%3}, {%4,%5,%6,%7}, {%8,%9}, {%0,%1,%2,%3};" \
                 : "+f"((c)[0]), "+f"((c)[1]), "+f"((c)[2]), "+f"((c)[3]) \
                 : "r"((a)[0]), "r"((a)[1]), "r"((a)[2]), "r"((a)[3]), "r"(b0), "r"(b1))

// split helpers
__device__ __forceinline__ void split4(float4 v, __nv_bfloat162& hA, __nv_bfloat162& hB,
                                       __nv_bfloat162& lA, __nv_bfloat162& lB) {
    __nv_bfloat16 h0 = __float2bfloat16(v.x), h1 = __float2bfloat16(v.y);
    __nv_bfloat16 h2 = __float2bfloat16(v.z), h3 = __float2bfloat16(v.w);
    __nv_bfloat16 l0 = __float2bfloat16(v.x - __bfloat162float(h0));
    __nv_bfloat16 l1 = __float2bfloat16(v.y - __bfloat162float(h1));
    __nv_bfloat16 l2 = __float2bfloat16(v.z - __bfloat162float(h2));
    __nv_bfloat16 l3 = __float2bfloat16(v.w - __bfloat162float(h3));
    hA = {h0, h1}; hB = {h2, h3}; lA = {l0, l1}; lB = {l2, l3};
}

// ---------------- W split: g_Wb[n] = [hi | lo | hi]
__global__ void convW(const float* __restrict__ W) {
    size_t i = (size_t)blockIdx.x * 1024 + threadIdx.x;
    float4 v = ((const float4*)W)[i];
    size_t n = i >> 8;
    size_t k4 = (i & 255) * 4;
    __nv_bfloat162 hA, hB, lA, lB;
    split4(v, hA, hB, lA, lB);
    __nv_bfloat16* dst = g_Wb + n * KTOT;
    *(__nv_bfloat162*)(dst + k4) = hA;          *(__nv_bfloat162*)(dst + k4 + 2) = hB;
    *(__nv_bfloat162*)(dst + 1024 + k4) = lA;   *(__nv_bfloat162*)(dst + 1024 + k4 + 2) = lB;
    *(__nv_bfloat162*)(dst + 2048 + k4) = hA;   *(__nv_bfloat162*)(dst + 2048 + k4 + 2) = hB;
}

// ---------------- pred split: g_Ab[m] = [hi | hi | lo]
__global__ void convA() {
    size_t i = (size_t)blockIdx.x * 1024 + threadIdx.x;
    float4 v = ((const float4*)g_pred)[i];
    size_t m = i >> 8;
    size_t k4 = (i & 255) * 4;
    __nv_bfloat162 hA, hB, lA, lB;
    split4(v, hA, hB, lA, lB);
    __nv_bfloat16* dst = g_Ab + m * KTOT;
    *(__nv_bfloat162*)(dst + k4) = hA;          *(__nv_bfloat162*)(dst + k4 + 2) = hB;
    *(__nv_bfloat162*)(dst + 1024 + k4) = hA;   *(__nv_bfloat162*)(dst + 1024 + k4 + 2) = hB;
    *(__nv_bfloat162*)(dst + 2048 + k4) = lA;   *(__nv_bfloat162*)(dst + 2048 + k4 + 2) = lB;
}

// ---------------- gather embedding rows + split
__global__ void gatherX(const float* __restrict__ emb, const int* __restrict__ tok,
                        int L, int which) {
    __nv_bfloat16* X = which ? g_Xd : g_Xe;
    int m = blockIdx.x * 8 + (threadIdx.x >> 5);
    int lane = threadIdx.x & 31;
    int t = m >> 5, b = m & 31;
    int tv = tok[b * L + t];
    const float4* er = (const float4*)(emb + (size_t)tv * EE);
    __nv_bfloat16* dst = X + (size_t)m * GIK;
    #pragma unroll
    for (int q = 0; q < 2; q++) {
        float4 v = er[lane * 2 + q];
        int e = lane * 8 + q * 4;
        __nv_bfloat162 hA, hB, lA, lB;
        split4(v, hA, hB, lA, lB);
        *(__nv_bfloat162*)(dst + e) = hA;            *(__nv_bfloat162*)(dst + e + 2) = hB;
        *(__nv_bfloat162*)(dst + 256 + e) = hA;      *(__nv_bfloat162*)(dst + 256 + e + 2) = hB;
        *(__nv_bfloat162*)(dst + 512 + e) = lA;      *(__nv_bfloat162*)(dst + 512 + e + 2) = lB;
    }
}

// ---------------- split Wih rows (first 256 cols)
__global__ void splitWih(const float* __restrict__ W, int stride, int which) {
    __nv_bfloat16* out = which ? g_Wd : g_We;
    int j = blockIdx.x * 8 + (threadIdx.x >> 5);
    int lane = threadIdx.x & 31;
    const float4* wr = (const float4*)(W + (size_t)j * stride);
    __nv_bfloat16* dst = out + (size_t)j * GIK;
    #pragma unroll
    for (int q = 0; q < 2; q++) {
        float4 v = wr[lane * 2 + q];
        int e = lane * 8 + q * 4;
        __nv_bfloat162 hA, hB, lA, lB;
        split4(v, hA, hB, lA, lB);
        *(__nv_bfloat162*)(dst + e) = hA;            *(__nv_bfloat162*)(dst + e + 2) = hB;
        *(__nv_bfloat162*)(dst + 256 + e) = lA;      *(__nv_bfloat162*)(dst + 256 + e + 2) = lB;
        *(__nv_bfloat162*)(dst + 512 + e) = hA;      *(__nv_bfloat162*)(dst + 512 + e + 2) = hB;
    }
}

// ---------------- gi GEMM via HMMA (256 thr, 128x128)
__global__ void __launch_bounds__(256) gi_mma(const float* __restrict__ bih, int which) {
    extern __shared__ uint8_t dynsmem[];
    uint32_t sA = smem_u32(dynsmem);
    uint32_t sB = sA + 2 * GBUF_B;

    const __nv_bfloat16* A = which ? g_Xd : g_Xe;
    const __nv_bfloat16* Bm = which ? g_Wd : g_We;
    float* outg = which ? g_dec_gie : g_enc_gi;

    int tid = threadIdx.x;
    int wid = tid >> 5, lane = tid & 31;
    int wm = wid & 3, wn = wid >> 2;
    int m0 = blockIdx.x * GBM;
    int n0 = blockIdx.y * GBN;

    const char* Ag = (const char*)(A + (size_t)m0 * GIK);
    const char* Bg = (const char*)(Bm + (size_t)n0 * GIK);
    int lrow = tid >> 3, lu = tid & 7;

    auto load_chunk = [&](int kc, int s) {
        uint32_t sa = sA + s * GBUF_B;
        uint32_t sbm = sB + s * GBUF_B;
        size_t gk = (size_t)kc * GBK * 2;
        #pragma unroll
        for (int it = 0; it < 4; it++) {
            int row = it * 32 + lrow;
            uint32_t doff = (uint32_t)(row * (GLDA * 2) + lu * 16);
            cpasync16(sa + doff, Ag + (size_t)row * (GIK * 2) + gk + lu * 16);
            cpasync16(sbm + doff, Bg + (size_t)row * (GIK * 2) + gk + lu * 16);
        }
        asm volatile("cp.async.commit_group;" ::: "memory");
    };

    float acc[2][8][4];
    #pragma unroll
    for (int a = 0; a < 2; a++)
        #pragma unroll
        for (int b = 0; b < 8; b++)
            #pragma unroll
            for (int c = 0; c < 4; c++) acc[a][b][c] = 0.0f;

    uint32_t aBase = (uint32_t)(((wm * 32 + (lane & 15)) * GLDA + (lane >> 4) * 8) * 2);
    uint32_t bBase = (uint32_t)(((wn * 64 + (lane & 7) + ((lane >> 4) & 1) * 8) * GLDA
                                 + ((lane >> 3) & 1) * 8) * 2);

    load_chunk(0, 0);
    for (int kc = 0; kc < GINC; kc++) {
        int s = kc & 1;
        if (kc + 1 < GINC) {
            load_chunk(kc + 1, s ^ 1);
            asm volatile("cp.async.wait_group 1;" ::: "memory");
        } else {
            asm volatile("cp.async.wait_group 0;" ::: "memory");
        }
        __syncthreads();
        uint32_t sa = sA + s * GBUF_B + aBase;
        uint32_t sbm = sB + s * GBUF_B + bBase;
        #pragma unroll
        for (int ks = 0; ks < 4; ks++) {
            uint32_t koff = (uint32_t)(ks * 16 * 2);
            uint32_t a0[4], a1[4];
            LDSM4(a0[0], a0[1], a0[2], a0[3], sa + koff);
            LDSM4(a1[0], a1[1], a1[2], a1[3], sa + 16 * GLDA * 2 + koff);
            uint32_t bf[16];
            #pragma unroll
            for (int nt = 0; nt < 4; nt++)
                LDSM4(bf[nt * 4 + 0], bf[nt * 4 + 1], bf[nt * 4 + 2], bf[nt * 4 + 3],
                      sbm + nt * 16 * GLDA * 2 + koff);
            #pragma unroll
            for (int j = 0; j < 8; j++) {
                int nt = j >> 1, hf = j & 1;
                MMA16816(acc[0][j], a0, bf[nt * 4 + hf * 2], bf[nt * 4 + hf * 2 + 1]);
                MMA16816(acc[1][j], a1, bf[nt * 4 + hf * 2], bf[nt * 4 + hf * 2 + 1]);
            }
        }
        __syncthreads();
    }

    #pragma unroll
    for (int mt = 0; mt < 2; mt++) {
        #pragma unroll
        for (int half = 0; half < 2; half++) {
            int m = m0 + wm * 32 + mt * 16 + (lane >> 2) + half * 8;
            int t = m >> 5, b = m & 31;
            float* obase = outg + (size_t)t * (H3 * BB) + b;
            #pragma unroll
            for (int j = 0; j < 8; j++) {
                int n = n0 + wn * 64 + j * 8 + (lane & 3) * 2;
                obase[(size_t)n * 32] = acc[mt][j][half * 2 + 0] + __ldg(bih + n);
                obase[(size_t)(n + 1) * 32] = acc[mt][j][half * 2 + 1] + __ldg(bih + n + 1);
            }
        }
    }
}

// ---------------- encoder scan ----------------
__global__ void __launch_bounds__(512) enc_scan(const float* __restrict__ Whh,
                                                const float* __restrict__ bhh) {
    int wid = threadIdx.x >> 5, lane = threadIdx.x & 31;
    int iLocal = wid & 3;
    int kq = wid >> 2;
    int i = blockIdx.x * 4 + iLocal;
    __shared__ float ps[4][3][3][32];

    for (int t = 0; t < SS; t++) {
        const float* hprev = t ? (g_eo + (t - 1) * (HH * BB)) : g_h0;
        float s0 = 0, s1 = 0, s2 = 0;
        {
            const float4* w0 = (const float4*)(Whh + (long)(i) * HH + kq * 128);
            const float4* w1 = (const float4*)(Whh + (long)(HH + i) * HH + kq * 128);
            const float4* w2 = (const float4*)(Whh + (long)(2 * HH + i) * HH + kq * 128);
            const float* hp = hprev + kq * 128 * 32 + lane;
            #pragma unroll 4
            for (int q = 0; q < 32; q++) {
                float h0 = hp[q * 128 + 0];
                float h1 = hp[q * 128 + 32];
                float h2 = hp[q * 128 + 64];
                float h3 = hp[q * 128 + 96];
                float4 w;
                w = w0[q]; s0 += w.x * h0 + w.y * h1 + w.z * h2 + w.w * h3;
                w = w1[q]; s1 += w.x * h0 + w.y * h1 + w.z * h2 + w.w * h3;
                w = w2[q]; s2 += w.x * h0 + w.y * h1 + w.z * h2 + w.w * h3;
            }
        }
        if (kq > 0) {
            ps[iLocal][kq - 1][0][lane] = s0;
            ps[iLocal][kq - 1][1][lane] = s1;
            ps[iLocal][kq - 1][2][lane] = s2;
        }
        __syncthreads();
        if (wid < 4) {
            float rh = s0 + ps[wid][0][0][lane] + ps[wid][1][0][lane] + ps[wid][2][0][lane] + bhh[i];
            float zh = s1 + ps[wid][0][1][lane] + ps[wid][1][1][lane] + ps[wid][2][1][lane] + bhh[HH + i];
            float nh = s2 + ps[wid][0][2][lane] + ps[wid][1][2][lane] + ps[wid][2][2][lane] + bhh[2 * HH + i];
            const float* gi = g_enc_gi + t * (H3 * BB);
            float ir = gi[i * 32 + lane];
            float iz = gi[(HH + i) * 32 + lane];
            float in_ = gi[(2 * HH + i) * 32 + lane];
            float r = sigm(ir + rh);
            float z = sigm(iz + zh);
            float n = tanhf(in_ + r * nh);
            float hv = hprev[i * 32 + lane];
            g_eo[t * (HH * BB) + i * 32 + lane] = (1.0f - z) * n + z * hv;
        }
        grid_sync(gridDim.x);
    }
}

__global__ void copyh() {
    int idx = blockIdx.x * 1024 + threadIdx.x;
    if (idx < HH * BB) g_hdec[0][idx] = g_eo[(SS - 1) * (HH * BB) + idx];
}

// ---------------- decoder scan ----------------
__global__ void __launch_bounds__(512) dec_scan(const float* __restrict__ Whh,
                                                const float* __restrict__ bhh,
                                                const float* __restrict__ Wih,
                                                const int* __restrict__ src) {
    int wid = threadIdx.x >> 5, lane = threadIdx.x & 31;
    __shared__ float psA[2][8][32];
    __shared__ float psC[4][4][32];
    __shared__ float denS[32];
    __shared__ float psD[4][3][6][32];

    for (int t = 0; t < TT; t++) {
        const float* h = g_hdec[t & 1];
        {
            int s = blockIdx.x * 2 + (wid & 1);
            int kq8 = wid >> 1;
            float acc = 0.0f;
            const float* eo = g_eo + s * (HH * BB) + kq8 * 64 * 32 + lane;
            const float* hp = h + kq8 * 64 * 32 + lane;
            #pragma unroll 8
            for (int k = 0; k < 64; k++) acc += eo[k * 32] * hp[k * 32];
            psA[wid & 1][kq8][lane] = acc;
            __syncthreads();
            if (wid < 2) {
                int ss2 = blockIdx.x * 2 + wid;
                float sc = 0.0f;
                #pragma unroll
                for (int q = 0; q < 8; q++) sc += psA[wid][q][lane];
                int tokv = src[lane * SS + ss2];
                float e = (tokv == 0) ? 0.0f : __expf(sc);
                g_scores[ss2 * 32 + lane] = e;
            }
        }
        grid_sync(gridDim.x);
        {
            int k = blockIdx.x * 4 + (wid & 3);
            int sq = wid >> 2;
            float acc = 0.0f;
            const float* eo = g_eo + sq * 64 * (HH * BB) + k * 32 + lane;
            const float* sce = g_scores + sq * 64 * 32 + lane;
            #pragma unroll 8
            for (int s = 0; s < 64; s++) acc += sce[s * 32] * eo[s * (HH * BB)];
            psC[wid & 3][sq][lane] = acc;
            if (wid == 0) {
                float d = 0.0f;
                const float* sp = g_scores + lane;
                #pragma unroll 8
                for (int s = 0; s < SS; s++) d += sp[s * 32];
                denS[lane] = d;
            }
            __syncthreads();
            if (wid < 4) {
                int kk = blockIdx.x * 4 + wid;
                float c = (psC[wid][0][lane] + psC[wid][1][lane] + psC[wid][2][lane] + psC[wid][3][lane])
                          / denS[lane];
                g_ctx[kk * 32 + lane] = c;
                g_pred[(t * 32 + lane) * (2 * HH) + HH + kk] = c;
            }
        }
        grid_sync(gridDim.x);
        {
            int i = blockIdx.x * 4 + (wid & 3);
            int kq = wid >> 2;
            float a0 = 0, a1 = 0, a2 = 0, c0 = 0, c1 = 0, c2 = 0;
            {
                const float4* wh0 = (const float4*)(Whh + (long)(i) * HH + kq * 128);
                const float4* wh1 = (const float4*)(Whh + (long)(HH + i) * HH + kq * 128);
                const float4* wh2 = (const float4*)(Whh + (long)(2 * HH + i) * HH + kq * 128);
                const float4* wc0 = (const float4*)(Wih + (long)(i) * 768 + EE + kq * 128);
                const float4* wc1 = (const float4*)(Wih + (long)(HH + i) * 768 + EE + kq * 128);
                const float4* wc2 = (const float4*)(Wih + (long)(2 * HH + i) * 768 + EE + kq * 128);
                const float* hp = h + kq * 128 * 32 + lane;
                const float* cp = g_ctx + kq * 128 * 32 + lane;
                #pragma unroll 4
                for (int q = 0; q < 32; q++) {
                    float h0 = hp[q * 128 + 0], h1 = hp[q * 128 + 32];
                    float h2 = hp[q * 128 + 64], h3 = hp[q * 128 + 96];
                    float x0 = cp[q * 128 + 0], x1 = cp[q * 128 + 32];
                    float x2 = cp[q * 128 + 64], x3 = cp[q * 128 + 96];
                    float4 w;
                    w = wh0[q]; a0 += w.x * h0 + w.y * h1 + w.z * h2 + w.w * h3;
                    w = wh1[q]; a1 += w.x * h0 + w.y * h1 + w.z * h2 + w.w * h3;
                    w = wh2[q]; a2 += w.x * h0 + w.y * h1 + w.z * h2 + w.w * h3;
                    w = wc0[q]; c0 += w.x * x0 + w.y * x1 + w.z * x2 + w.w * x3;
                    w = wc1[q]; c1 += w.x * x0 + w.y * x1 + w.z * x2 + w.w * x3;
                    w = wc2[q]; c2 += w.x * x0 + w.y * x1 + w.z * x2 + w.w * x3;
                }
            }
            if (kq > 0) {
                psD[wid & 3][kq - 1][0][lane] = a0;
                psD[wid & 3][kq - 1][1][lane] = a1;
                psD[wid & 3][kq - 1][2][lane] = a2;
                psD[wid & 3][kq - 1][3][lane] = c0;
                psD[wid & 3][kq - 1][4][lane] = c1;
                psD[wid & 3][kq - 1][5][lane] = c2;
            }
            __syncthreads();
            if (wid < 4) {
                float rh = a0, zh = a1, nh = a2, rc = c0, zc = c1, nc = c2;
                #pragma unroll
                for (int kk = 0; kk < 3; kk++) {
                    rh += psD[wid][kk][0][lane];
                    zh += psD[wid][kk][1][lane];
                    nh += psD[wid][kk][2][lane];
                    rc += psD[wid][kk][3][lane];
                    zc += psD[wid][kk][4][lane];
                    nc += psD[wid][kk][5][lane];
                }
                rh += bhh[i]; zh += bhh[HH + i]; nh += bhh[2 * HH + i];
                const float* gie = g_dec_gie + t * (H3 * BB);
                float ir = gie[i * 32 + lane] + rc;
                float iz = gie[(HH + i) * 32 + lane] + zc;
                float in_ = gie[(2 * HH + i) * 32 + lane] + nc;
                float r = sigm(ir + rh);
                float z = sigm(iz + zh);
                float n = tanhf(in_ + r * nh);
                float hold = h[i * 32 + lane];
                float hn = (1.0f - z) * n + z * hold;
                g_hdec[(t + 1) & 1][i * 32 + lane] = hn;
                g_pred[(t * 32 + lane) * (2 * HH) + i] = hn;
            }
        }
        grid_sync(gridDim.x);
    }
}

// ---------------- fc GEMM via mma.sync: 512 thr, 128x256 tile, K=3072 ----------------
__global__ void __launch_bounds__(512) fc_mma(const float* __restrict__ bias,
                                              float* __restrict__ out) {
    extern __shared__ uint8_t dynsmem[];
    uint32_t sA = smem_u32(dynsmem);           // 2 x 18432
    uint32_t sB = sA + 2 * GBUF_B;             // 2 x 36864

    int tid = threadIdx.x;
    int wid = tid >> 5, lane = tid & 31;
    int wm = wid & 3, wn = wid >> 2;           // wm 0..3, wn 0..3
    int m0 = blockIdx.x * GBM;
    int n0 = blockIdx.y * FCBN;

    const char* Ag = (const char*)(g_Ab + (size_t)m0 * KTOT);
    const char* Bg = (const char*)(g_Wb + (size_t)n0 * KTOT);

    int lrow = tid >> 3, lu = tid & 7;         // lrow 0..63
    auto load_chunk = [&](int kc, int s) {
        uint32_t sa = sA + s * GBUF_B;
        uint32_t sbm = sB + s * FCBUF_B;
        size_t gk = (size_t)kc * GBK * 2;
        #pragma unroll
        for (int it = 0; it < 2; it++) {       // A: 128 rows
            int row = it * 64 + lrow;
            uint32_t doff = (uint32_t)(row * (GLDA * 2) + lu * 16);
            cpasync16(sa + doff, Ag + (size_t)row * (KTOT * 2) + gk + lu * 16);
        }
        #pragma unroll
        for (int it = 0; it < 4; it++) {       // B: 256 rows
            int row = it * 64 + lrow;
            uint32_t doff = (uint32_t)(row * (GLDA * 2) + lu * 16);
            cpasync16(sbm + doff, Bg + (size_t)row * (KTOT * 2) + gk + lu * 16);
        }
        asm volatile("cp.async.commit_group;" ::: "memory");
    };

    float acc[2][8][4];
    #pragma unroll
    for (int a = 0; a < 2; a++)
        #pragma unroll
        for (int b = 0; b < 8; b++)
            #pragma unroll
            for (int c = 0; c < 4; c++) acc[a][b][c] = 0.0f;

    uint32_t aBase = (uint32_t)(((wm * 32 + (lane & 15)) * GLDA + (lane >> 4) * 8) * 2);
    uint32_t bBase = (uint32_t)(((wn * 64 + (lane & 7) + ((lane >> 4) & 1) * 8) * GLDA
                                 + ((lane >> 3) & 1) * 8) * 2);

    load_chunk(0, 0);
    for (int kc = 0; kc < GNC; kc++) {
        int s = kc & 1;
        if (kc + 1 < GNC) {
            load_chunk(kc + 1, s ^ 1);
            asm volatile("cp.async.wait_group 1;" ::: "memory");
        } else {
            asm volatile("cp.async.wait_group 0;" ::: "memory");
        }
        __syncthreads();
        uint32_t sa = sA + s * GBUF_B + aBase;
        uint32_t sbm = sB + s * FCBUF_B + bBase;
        #pragma unroll
        for (int ks = 0; ks < 4; ks++) {
            uint32_t koff = (uint32_t)(ks * 16 * 2);
            uint32_t a0[4], a1[4];
            LDSM4(a0[0], a0[1], a0[2], a0[3], sa + koff);
            LDSM4(a1[0], a1[1], a1[2], a1[3], sa + 16 * GLDA * 2 + koff);
            uint32_t bf[16];
            #pragma unroll
            for (int nt = 0; nt < 4; nt++)
                LDSM4(bf[nt * 4 + 0], bf[nt * 4 + 1], bf[nt * 4 + 2], bf[nt * 4 + 3],
                      sbm + nt * 16 * GLDA * 2 + koff);
            #pragma unroll
            for (int j = 0; j < 8; j++) {
                int nt = j >> 1, hf = j & 1;
                MMA16816(acc[0][j], a0, bf[nt * 4 + hf * 2], bf[nt * 4 + hf * 2 + 1]);
                MMA16816(acc[1][j], a1, bf[nt * 4 + hf * 2], bf[nt * 4 + hf * 2 + 1]);
            }
        }
        __syncthreads();
    }

    float bv[8][2];
    #pragma unroll
    for (int j = 0; j < 8; j++) {
        int n = n0 + wn * 64 + j * 8 + (lane & 3) * 2;
        bv[j][0] = __ldg(bias + n);
        bv[j][1] = __ldg(bias + n + 1);
    }
    #pragma unroll
    for (int mt = 0; mt < 2; mt++) {
        #pragma unroll
        for (int half = 0; half < 2; half++) {
            int m = m0 + wm * 32 + mt * 16 + (lane >> 2) + half * 8;
            int t = m >> 5, b = m & 31;
            float* orow = out + (size_t)b * (TT * VV) + (size_t)t * VV;
            #pragma unroll
            for (int j = 0; j < 8; j++) {
                int n = n0 + wn * 64 + j * 8 + (lane & 3) * 2;
                float2 v;
                v.x = acc[mt][j][half * 2 + 0] + bv[j][0];
                v.y = acc[mt][j][half * 2 + 1] + bv[j][1];
                *(float2*)(orow + n) = v;
            }
        }
    }
}

// ---------------- launch ----------------
extern "C" void kernel_launch(void* const* d_in, const int* in_sizes, int n_in,
                              void* d_out, int out_size) {
    const int* src = (const int*)d_in[0];
    const int* tgt = (const int*)d_in[2];
    const float* enc_emb = (const float*)d_in[3];
    const float* enc_Wih = (const float*)d_in[4];
    const float* enc_Whh = (const float*)d_in[5];
    const float* enc_bih = (const float*)d_in[6];
    const float* enc_bhh = (const float*)d_in[7];
    const float* dec_emb = (const float*)d_in[8];
    const float* dec_Wih = (const float*)d_in[9];
    const float* dec_Whh = (const float*)d_in[10];
    const float* dec_bih = (const float*)d_in[11];
    const float* dec_bhh = (const float*)d_in[12];
    const float* fc_W = (const float*)d_in[13];
    const float* fc_b = (const float*)d_in[14];
    float* out = (float*)d_out;

    cudaFuncSetAttribute(fc_mma, cudaFuncAttributeMaxDynamicSharedMemorySize, FC_SMEM);
    cudaFuncSetAttribute(gi_mma, cudaFuncAttributeMaxDynamicSharedMemorySize, GI_SMEM);

    gatherX<<<SS * BB / 8, 256>>>(enc_emb, src, SS, 0);
    splitWih<<<H3 / 8, 256>>>(enc_Wih, EE, 0);
    gi_mma<<<dim3(SS * BB / GBM, H3 / GBN), 256, GI_SMEM>>>(enc_bih, 0);
    enc_scan<<<NCTA, 512>>>(enc_Whh, enc_bhh);
    gatherX<<<TT * BB / 8, 256>>>(dec_emb, tgt, TT, 1);
    splitWih<<<H3 / 8, 256>>>(dec_Wih, EE + HH, 1);
    gi_mma<<<dim3(TT * BB / GBM, H3 / GBN), 256, GI_SMEM>>>(dec_bih, 1);
    copyh<<<16, 1024>>>();
    dec_scan<<<NCTA, 512>>>(dec_Whh, dec_bhh, dec_Wih, src);
    convA<<<512, 1024>>>();
    convW<<<(VV * 1024) / 4096, 1024>>>(fc_W);
    fc_mma<<<dim3(TT * BB / GBM, VV / FCBN), 512, FC_SMEM>>>(fc_b, out);
}

// round 10
// speedup vs baseline: 1.1012x; 1.0247x over previous
#include <cuda_runtime.h>
#include <cuda_bf16.h>
#include <cstdint>

// Problem constants
#define BB 32
#define SS 256
#define TT 64
#define EE 256
#define HH 512
#define VV 32000
#define H3 1536

// GEMM tile config (both gi and fc): 128x128 tile, 256 thr, BK=64, 3-stage
#define GBM 128
#define GBN 128
#define GBK 64
#define GLDA 72                 // padded row (bf16 elems)
#define GBUF_B (GBM * GLDA * 2) // 18432 bytes per stage buffer
#define MM_SMEM (6 * GBUF_B)    // 110592 (3 stages x (A+B))

// K layouts (deduplicated): stored [hi | lo]
#define FCK 2048                // fc: pred/W rows
#define GIX 512                 // gi: emb/Wih rows
#define FC_NC 48                // 3 segments x 16 chunks
#define GI_NC 12                // 3 segments x 4 chunks

#define NCTA 128

// ---------------- scratch ----------------
__device__ float g_enc_gi[SS * H3 * BB];
__device__ float g_dec_gie[TT * H3 * BB];
__device__ float g_eo[SS * HH * BB];
__device__ float g_h0[HH * BB];          // never written -> stays zero
__device__ float g_hdec[2][HH * BB];
__device__ float g_ctx[HH * BB];
__device__ float g_scores[SS * BB];
__device__ float g_pred[(TT * BB) * (2 * HH)];
__device__ __nv_bfloat16 g_Wb[(size_t)VV * FCK];        // [hi|lo] 131MB
__device__ __nv_bfloat16 g_Ab[(size_t)(TT * BB) * FCK]; // [hi|lo]
__device__ __nv_bfloat16 g_Xe[(size_t)(SS * BB) * GIX];
__device__ __nv_bfloat16 g_Xd[(size_t)(TT * BB) * GIX];
__device__ __nv_bfloat16 g_We[(size_t)H3 * GIX];
__device__ __nv_bfloat16 g_Wd[(size_t)H3 * GIX];
__device__ unsigned g_bar_cnt;
__device__ unsigned g_bar_gen;

// ---------------- grid barrier (proven Round-1 implementation) ----------------
__device__ __forceinline__ void grid_sync(unsigned nb) {
    __syncthreads();
    if (threadIdx.x == 0) {
        __threadfence();
        volatile unsigned* genp = &g_bar_gen;
        unsigned gen = *genp;
        if (atomicAdd(&g_bar_cnt, 1u) == nb - 1u) {
            g_bar_cnt = 0;
            __threadfence();
            *genp = gen + 1u;
        } else {
            while (*genp == gen) { }
            __threadfence();
        }
    }
    __syncthreads();
}

__device__ __forceinline__ float sigm(float x) { return 1.0f / (1.0f + __expf(-x)); }

__device__ __forceinline__ uint32_t smem_u32(const void* p) {
    uint32_t a;
    asm("{ .reg .u64 t; cvta.to.shared.u64 t, %1; cvt.u32.u64 %0, t; }" : "=r"(a) : "l"(p));
    return a;
}
__device__ __forceinline__ void cpasync16(uint32_t dst, const void* src) {
    asm volatile("cp.async.cg.shared.global [%0], [%1], 16;" :: "r"(dst), "l"(src) : "memory");
}
#define LDSM4(r0, r1, r2, r3, addr) \
    asm volatile("ldmatrix.sync.aligned.m8n8.x4.shared.b16 {%0,%1,%2,%3}, [%4];" \
                 : "=r"(r0), "=r"(r1), "=r"(r2), "=r"(r3) : "r"(addr))
#define MMA16816(c, a, b0, b1) \
    asm volatile("mma.sync.aligned.m16n8k16.row.col.f32.bf16.bf16.f32 " \
                 "{%0,%1,%2,%3}, {%4,%5,%6,%7}, {%8,%9}, {%0,%1,%2,%3};" \
                 : "+f"((c)[0]), "+f"((c)[1]), "+f"((c)[2]), "+f"((c)[3]) \
                 : "r"((a)[0]), "r"((a)[1]), "r"((a)[2]), "r"((a)[3]), "r"(b0), "r"(b1))

// split helpers
__device__ __forceinline__ void split4(float4 v, __nv_bfloat162& hA, __nv_bfloat162& hB,
                                       __nv_bfloat162& lA, __nv_bfloat162& lB) {
    __nv_bfloat16 h0 = __float2bfloat16(v.x), h1 = __float2bfloat16(v.y);
    __nv_bfloat16 h2 = __float2bfloat16(v.z), h3 = __float2bfloat16(v.w);
    __nv_bfloat16 l0 = __float2bfloat16(v.x - __bfloat162float(h0));
    __nv_bfloat16 l1 = __float2bfloat16(v.y - __bfloat162float(h1));
    __nv_bfloat16 l2 = __float2bfloat16(v.z - __bfloat162float(h2));
    __nv_bfloat16 l3 = __float2bfloat16(v.w - __bfloat162float(h3));
    hA = {h0, h1}; hB = {h2, h3}; lA = {l0, l1}; lB = {l2, l3};
}

// ---------------- W split: g_Wb[n] = [hi(1024) | lo(1024)]
__global__ void convW(const float* __restrict__ W) {
    size_t i = (size_t)blockIdx.x * 1024 + threadIdx.x;
    float4 v = ((const float4*)W)[i];
    size_t n = i >> 8;
    size_t k4 = (i & 255) * 4;
    __nv_bfloat162 hA, hB, lA, lB;
    split4(v, hA, hB, lA, lB);
    __nv_bfloat16* dst = g_Wb + n * FCK;
    *(__nv_bfloat162*)(dst + k4) = hA;          *(__nv_bfloat162*)(dst + k4 + 2) = hB;
    *(__nv_bfloat162*)(dst + 1024 + k4) = lA;   *(__nv_bfloat162*)(dst + 1024 + k4 + 2) = lB;
}

// ---------------- pred split: g_Ab[m] = [hi | lo]
__global__ void convA() {
    size_t i = (size_t)blockIdx.x * 1024 + threadIdx.x;
    float4 v = ((const float4*)g_pred)[i];
    size_t m = i >> 8;
    size_t k4 = (i & 255) * 4;
    __nv_bfloat162 hA, hB, lA, lB;
    split4(v, hA, hB, lA, lB);
    __nv_bfloat16* dst = g_Ab + m * FCK;
    *(__nv_bfloat162*)(dst + k4) = hA;          *(__nv_bfloat162*)(dst + k4 + 2) = hB;
    *(__nv_bfloat162*)(dst + 1024 + k4) = lA;   *(__nv_bfloat162*)(dst + 1024 + k4 + 2) = lB;
}

// ---------------- gather embedding rows + split: X[m] = [hi(256) | lo(256)]
__global__ void gatherX(const float* __restrict__ emb, const int* __restrict__ tok,
                        int L, int which) {
    __nv_bfloat16* X = which ? g_Xd : g_Xe;
    int m = blockIdx.x * 8 + (threadIdx.x >> 5);
    int lane = threadIdx.x & 31;
    int t = m >> 5, b = m & 31;
    int tv = tok[b * L + t];
    const float4* er = (const float4*)(emb + (size_t)tv * EE);
    __nv_bfloat16* dst = X + (size_t)m * GIX;
    #pragma unroll
    for (int q = 0; q < 2; q++) {
        float4 v = er[lane * 2 + q];
        int e = lane * 8 + q * 4;
        __nv_bfloat162 hA, hB, lA, lB;
        split4(v, hA, hB, lA, lB);
        *(__nv_bfloat162*)(dst + e) = hA;            *(__nv_bfloat162*)(dst + e + 2) = hB;
        *(__nv_bfloat162*)(dst + 256 + e) = lA;      *(__nv_bfloat162*)(dst + 256 + e + 2) = lB;
    }
}

// ---------------- split Wih rows (first 256 cols): out[j] = [hi | lo]
__global__ void splitWih(const float* __restrict__ W, int stride, int which) {
    __nv_bfloat16* out = which ? g_Wd : g_We;
    int j = blockIdx.x * 8 + (threadIdx.x >> 5);
    int lane = threadIdx.x & 31;
    const float4* wr = (const float4*)(W + (size_t)j * stride);
    __nv_bfloat16* dst = out + (size_t)j * GIX;
    #pragma unroll
    for (int q = 0; q < 2; q++) {
        float4 v = wr[lane * 2 + q];
        int e = lane * 8 + q * 4;
        __nv_bfloat162 hA, hB, lA, lB;
        split4(v, hA, hB, lA, lB);
        *(__nv_bfloat162*)(dst + e) = hA;            *(__nv_bfloat162*)(dst + e + 2) = hB;
        *(__nv_bfloat162*)(dst + 256 + e) = lA;      *(__nv_bfloat162*)(dst + 256 + e + 2) = lB;
    }
}

// ---------------- shared GEMM mainloop body (macro-free, templated by params) ----
// Segments: 0=(Ah,Wh) 1=(Ah,Wl) 2=(Al,Wh). seg offsets in ELEMENTS.
// ---------------- gi GEMM via HMMA (256 thr, 128x128, K eff 768)
__global__ void __launch_bounds__(256) gi_mma(const float* __restrict__ bih, int which) {
    extern __shared__ uint8_t dynsmem[];
    uint32_t sA = smem_u32(dynsmem);           // 3 stages
    uint32_t sB = sA + 3 * GBUF_B;

    const __nv_bfloat16* A = which ? g_Xd : g_Xe;
    const __nv_bfloat16* Bm = which ? g_Wd : g_We;
    float* outg = which ? g_dec_gie : g_enc_gi;

    int tid = threadIdx.x;
    int wid = tid >> 5, lane = tid & 31;
    int wm = wid & 3, wn = wid >> 2;
    int m0 = blockIdx.x * GBM;
    int n0 = blockIdx.y * GBN;

    const char* Ag = (const char*)(A + (size_t)m0 * GIX);
    const char* Bg = (const char*)(Bm + (size_t)n0 * GIX);
    int lrow = tid >> 3, lu = tid & 7;

    auto load_chunk = [&](int kc, int st) {
        int seg = kc >> 2, c = kc & 3;
        size_t aoff = (size_t)(((seg == 2) ? 256 : 0) + c * 64) * 2;   // bytes
        size_t boff = (size_t)(((seg == 1) ? 256 : 0) + c * 64) * 2;
        uint32_t sa = sA + st * GBUF_B;
        uint32_t sbm = sB + st * GBUF_B;
        #pragma unroll
        for (int it = 0; it < 4; it++) {
            int row = it * 32 + lrow;
            uint32_t doff = (uint32_t)(row * (GLDA * 2) + lu * 16);
            cpasync16(sa + doff, Ag + (size_t)row * (GIX * 2) + aoff + lu * 16);
            cpasync16(sbm + doff, Bg + (size_t)row * (GIX * 2) + boff + lu * 16);
        }
        asm volatile("cp.async.commit_group;" ::: "memory");
    };

    float acc[2][8][4];
    #pragma unroll
    for (int a = 0; a < 2; a++)
        #pragma unroll
        for (int b = 0; b < 8; b++)
            #pragma unroll
            for (int c = 0; c < 4; c++) acc[a][b][c] = 0.0f;

    uint32_t aBase = (uint32_t)(((wm * 32 + (lane & 15)) * GLDA + (lane >> 4) * 8) * 2);
    uint32_t bBase = (uint32_t)(((wn * 64 + (lane & 7) + ((lane >> 4) & 1) * 8) * GLDA
                                 + ((lane >> 3) & 1) * 8) * 2);

    load_chunk(0, 0);
    load_chunk(1, 1);
    for (int kc = 0; kc < GI_NC; kc++) {
        int st = kc % 3;
        if (kc == GI_NC - 1) { asm volatile("cp.async.wait_group 0;" ::: "memory"); }
        else                 { asm volatile("cp.async.wait_group 1;" ::: "memory"); }
        __syncthreads();
        if (kc + 2 < GI_NC) load_chunk(kc + 2, (kc + 2) % 3);
        uint32_t sa = sA + st * GBUF_B + aBase;
        uint32_t sbm = sB + st * GBUF_B + bBase;
        #pragma unroll
        for (int ks = 0; ks < 4; ks++) {
            uint32_t koff = (uint32_t)(ks * 16 * 2);
            uint32_t a0[4], a1[4];
            LDSM4(a0[0], a0[1], a0[2], a0[3], sa + koff);
            LDSM4(a1[0], a1[1], a1[2], a1[3], sa + 16 * GLDA * 2 + koff);
            uint32_t bf[16];
            #pragma unroll
            for (int nt = 0; nt < 4; nt++)
                LDSM4(bf[nt * 4 + 0], bf[nt * 4 + 1], bf[nt * 4 + 2], bf[nt * 4 + 3],
                      sbm + nt * 16 * GLDA * 2 + koff);
            #pragma unroll
            for (int j = 0; j < 8; j++) {
                int nt = j >> 1, hf = j & 1;
                MMA16816(acc[0][j], a0, bf[nt * 4 + hf * 2], bf[nt * 4 + hf * 2 + 1]);
                MMA16816(acc[1][j], a1, bf[nt * 4 + hf * 2], bf[nt * 4 + hf * 2 + 1]);
            }
        }
    }
    __syncthreads();

    #pragma unroll
    for (int mt = 0; mt < 2; mt++) {
        #pragma unroll
        for (int half = 0; half < 2; half++) {
            int m = m0 + wm * 32 + mt * 16 + (lane >> 2) + half * 8;
            int t = m >> 5, b = m & 31;
            float* obase = outg + (size_t)t * (H3 * BB) + b;
            #pragma unroll
            for (int j = 0; j < 8; j++) {
                int n = n0 + wn * 64 + j * 8 + (lane & 3) * 2;
                obase[(size_t)n * 32] = acc[mt][j][half * 2 + 0] + __ldg(bih + n);
                obase[(size_t)(n + 1) * 32] = acc[mt][j][half * 2 + 1] + __ldg(bih + n + 1);
            }
        }
    }
}

// ---------------- encoder scan ----------------
__global__ void __launch_bounds__(512) enc_scan(const float* __restrict__ Whh,
                                                const float* __restrict__ bhh) {
    int wid = threadIdx.x >> 5, lane = threadIdx.x & 31;
    int iLocal = wid & 3;
    int kq = wid >> 2;
    int i = blockIdx.x * 4 + iLocal;
    __shared__ float ps[4][3][3][32];

    for (int t = 0; t < SS; t++) {
        const float* hprev = t ? (g_eo + (t - 1) * (HH * BB)) : g_h0;
        float s0 = 0, s1 = 0, s2 = 0;
        {
            const float4* w0 = (const float4*)(Whh + (long)(i) * HH + kq * 128);
            const float4* w1 = (const float4*)(Whh + (long)(HH + i) * HH + kq * 128);
            const float4* w2 = (const float4*)(Whh + (long)(2 * HH + i) * HH + kq * 128);
            const float* hp = hprev + kq * 128 * 32 + lane;
            #pragma unroll 4
            for (int q = 0; q < 32; q++) {
                float h0 = hp[q * 128 + 0];
                float h1 = hp[q * 128 + 32];
                float h2 = hp[q * 128 + 64];
                float h3 = hp[q * 128 + 96];
                float4 w;
                w = w0[q]; s0 += w.x * h0 + w.y * h1 + w.z * h2 + w.w * h3;
                w = w1[q]; s1 += w.x * h0 + w.y * h1 + w.z * h2 + w.w * h3;
                w = w2[q]; s2 += w.x * h0 + w.y * h1 + w.z * h2 + w.w * h3;
            }
        }
        if (kq > 0) {
            ps[iLocal][kq - 1][0][lane] = s0;
            ps[iLocal][kq - 1][1][lane] = s1;
            ps[iLocal][kq - 1][2][lane] = s2;
        }
        __syncthreads();
        if (wid < 4) {
            float rh = s0 + ps[wid][0][0][lane] + ps[wid][1][0][lane] + ps[wid][2][0][lane] + bhh[i];
            float zh = s1 + ps[wid][0][1][lane] + ps[wid][1][1][lane] + ps[wid][2][1][lane] + bhh[HH + i];
            float nh = s2 + ps[wid][0][2][lane] + ps[wid][1][2][lane] + ps[wid][2][2][lane] + bhh[2 * HH + i];
            const float* gi = g_enc_gi + t * (H3 * BB);
            float ir = gi[i * 32 + lane];
            float iz = gi[(HH + i) * 32 + lane];
            float in_ = gi[(2 * HH + i) * 32 + lane];
            float r = sigm(ir + rh);
            float z = sigm(iz + zh);
            float n = tanhf(in_ + r * nh);
            float hv = hprev[i * 32 + lane];
            g_eo[t * (HH * BB) + i * 32 + lane] = (1.0f - z) * n + z * hv;
        }
        grid_sync(gridDim.x);
    }
}

// ---------------- decoder scan (copyh folded: t=0 reads last enc step) --------
__global__ void __launch_bounds__(512) dec_scan(const float* __restrict__ Whh,
                                                const float* __restrict__ bhh,
                                                const float* __restrict__ Wih,
                                                const int* __restrict__ src) {
    int wid = threadIdx.x >> 5, lane = threadIdx.x & 31;
    __shared__ float psA[2][8][32];
    __shared__ float psC[4][4][32];
    __shared__ float denS[32];
    __shared__ float psD[4][3][6][32];

    for (int t = 0; t < TT; t++) {
        const float* h = t ? g_hdec[t & 1] : (g_eo + (SS - 1) * (HH * BB));
        {
            int s = blockIdx.x * 2 + (wid & 1);
            int kq8 = wid >> 1;
            float acc = 0.0f;
            const float* eo = g_eo + s * (HH * BB) + kq8 * 64 * 32 + lane;
            const float* hp = h + kq8 * 64 * 32 + lane;
            #pragma unroll 8
            for (int k = 0; k < 64; k++) acc += eo[k * 32] * hp[k * 32];
            psA[wid & 1][kq8][lane] = acc;
            __syncthreads();
            if (wid < 2) {
                int ss2 = blockIdx.x * 2 + wid;
                float sc = 0.0f;
                #pragma unroll
                for (int q = 0; q < 8; q++) sc += psA[wid][q][lane];
                int tokv = src[lane * SS + ss2];
                float e = (tokv == 0) ? 0.0f : __expf(sc);
                g_scores[ss2 * 32 + lane] = e;
            }
        }
        grid_sync(gridDim.x);
        {
            int k = blockIdx.x * 4 + (wid & 3);
            int sq = wid >> 2;
            float acc = 0.0f;
            const float* eo = g_eo + sq * 64 * (HH * BB) + k * 32 + lane;
            const float* sce = g_scores + sq * 64 * 32 + lane;
            #pragma unroll 8
            for (int s = 0; s < 64; s++) acc += sce[s * 32] * eo[s * (HH * BB)];
            psC[wid & 3][sq][lane] = acc;
            if (wid == 0) {
                float d = 0.0f;
                const float* sp = g_scores + lane;
                #pragma unroll 8
                for (int s = 0; s < SS; s++) d += sp[s * 32];
                denS[lane] = d;
            }
            __syncthreads();
            if (wid < 4) {
                int kk = blockIdx.x * 4 + wid;
                float c = (psC[wid][0][lane] + psC[wid][1][lane] + psC[wid][2][lane] + psC[wid][3][lane])
                          / denS[lane];
                g_ctx[kk * 32 + lane] = c;
                g_pred[(t * 32 + lane) * (2 * HH) + HH + kk] = c;
            }
        }
        grid_sync(gridDim.x);
        {
            int i = blockIdx.x * 4 + (wid & 3);
            int kq = wid >> 2;
            float a0 = 0, a1 = 0, a2 = 0, c0 = 0, c1 = 0, c2 = 0;
            {
                const float4* wh0 = (const float4*)(Whh + (long)(i) * HH + kq * 128);
                const float4* wh1 = (const float4*)(Whh + (long)(HH + i) * HH + kq * 128);
                const float4* wh2 = (const float4*)(Whh + (long)(2 * HH + i) * HH + kq * 128);
                const float4* wc0 = (const float4*)(Wih + (long)(i) * 768 + EE + kq * 128);
                const float4* wc1 = (const float4*)(Wih + (long)(HH + i) * 768 + EE + kq * 128);
                const float4* wc2 = (const float4*)(Wih + (long)(2 * HH + i) * 768 + EE + kq * 128);
                const float* hp = h + kq * 128 * 32 + lane;
                const float* cp = g_ctx + kq * 128 * 32 + lane;
                #pragma unroll 4
                for (int q = 0; q < 32; q++) {
                    float h0 = hp[q * 128 + 0], h1 = hp[q * 128 + 32];
                    float h2 = hp[q * 128 + 64], h3 = hp[q * 128 + 96];
                    float x0 = cp[q * 128 + 0], x1 = cp[q * 128 + 32];
                    float x2 = cp[q * 128 + 64], x3 = cp[q * 128 + 96];
                    float4 w;
                    w = wh0[q]; a0 += w.x * h0 + w.y * h1 + w.z * h2 + w.w * h3;
                    w = wh1[q]; a1 += w.x * h0 + w.y * h1 + w.z * h2 + w.w * h3;
                    w = wh2[q]; a2 += w.x * h0 + w.y * h1 + w.z * h2 + w.w * h3;
                    w = wc0[q]; c0 += w.x * x0 + w.y * x1 + w.z * x2 + w.w * x3;
                    w = wc1[q]; c1 += w.x * x0 + w.y * x1 + w.z * x2 + w.w * x3;
                    w = wc2[q]; c2 += w.x * x0 + w.y * x1 + w.z * x2 + w.w * x3;
                }
            }
            if (kq > 0) {
                psD[wid & 3][kq - 1][0][lane] = a0;
                psD[wid & 3][kq - 1][1][lane] = a1;
                psD[wid & 3][kq - 1][2][lane] = a2;
                psD[wid & 3][kq - 1][3][lane] = c0;
                psD[wid & 3][kq - 1][4][lane] = c1;
                psD[wid & 3][kq - 1][5][lane] = c2;
            }
            __syncthreads();
            if (wid < 4) {
                float rh = a0, zh = a1, nh = a2, rc = c0, zc = c1, nc = c2;
                #pragma unroll
                for (int kk = 0; kk < 3; kk++) {
                    rh += psD[wid][kk][0][lane];
                    zh += psD[wid][kk][1][lane];
                    nh += psD[wid][kk][2][lane];
                    rc += psD[wid][kk][3][lane];
                    zc += psD[wid][kk][4][lane];
                    nc += psD[wid][kk][5][lane];
                }
                rh += bhh[i]; zh += bhh[HH + i]; nh += bhh[2 * HH + i];
                const float* gie = g_dec_gie + t * (H3 * BB);
                float ir = gie[i * 32 + lane] + rc;
                float iz = gie[(HH + i) * 32 + lane] + zc;
                float in_ = gie[(2 * HH + i) * 32 + lane] + nc;
                float r = sigm(ir + rh);
                float z = sigm(iz + zh);
                float n = tanhf(in_ + r * nh);
                float hold = h[i * 32 + lane];
                float hn = (1.0f - z) * n + z * hold;
                g_hdec[(t + 1) & 1][i * 32 + lane] = hn;
                g_pred[(t * 32 + lane) * (2 * HH) + i] = hn;
            }
        }
        grid_sync(gridDim.x);
    }
}

// ---------------- fc GEMM via mma.sync (256 thr, 128x128, K eff 3072) ----------
__global__ void __launch_bounds__(256) fc_mma(const float* __restrict__ bias,
                                              float* __restrict__ out) {
    extern __shared__ uint8_t dynsmem[];
    uint32_t sA = smem_u32(dynsmem);           // 3 stages
    uint32_t sB = sA + 3 * GBUF_B;

    int tid = threadIdx.x;
    int wid = tid >> 5, lane = tid & 31;
    int wm = wid & 3, wn = wid >> 2;
    int m0 = blockIdx.x * GBM;
    int n0 = blockIdx.y * GBN;

    const char* Ag = (const char*)(g_Ab + (size_t)m0 * FCK);
    const char* Bg = (const char*)(g_Wb + (size_t)n0 * FCK);
    int lrow = tid >> 3, lu = tid & 7;

    auto load_chunk = [&](int kc, int st) {
        int seg = kc >> 4, c = kc & 15;
        size_t aoff = (size_t)(((seg == 2) ? 1024 : 0) + c * 64) * 2;   // bytes
        size_t boff = (size_t)(((seg == 1) ? 1024 : 0) + c * 64) * 2;
        uint32_t sa = sA + st * GBUF_B;
        uint32_t sbm = sB + st * GBUF_B;
        #pragma unroll
        for (int it = 0; it < 4; it++) {
            int row = it * 32 + lrow;
            uint32_t doff = (uint32_t)(row * (GLDA * 2) + lu * 16);
            cpasync16(sa + doff, Ag + (size_t)row * (FCK * 2) + aoff + lu * 16);
            cpasync16(sbm + doff, Bg + (size_t)row * (FCK * 2) + boff + lu * 16);
        }
        asm volatile("cp.async.commit_group;" ::: "memory");
    };

    float acc[2][8][4];
    #pragma unroll
    for (int a = 0; a < 2; a++)
        #pragma unroll
        for (int b = 0; b < 8; b++)
            #pragma unroll
            for (int c = 0; c < 4; c++) acc[a][b][c] = 0.0f;

    uint32_t aBase = (uint32_t)(((wm * 32 + (lane & 15)) * GLDA + (lane >> 4) * 8) * 2);
    uint32_t bBase = (uint32_t)(((wn * 64 + (lane & 7) + ((lane >> 4) & 1) * 8) * GLDA
                                 + ((lane >> 3) & 1) * 8) * 2);

    load_chunk(0, 0);
    load_chunk(1, 1);
    for (int kc = 0; kc < FC_NC; kc++) {
        int st = kc % 3;
        if (kc == FC_NC - 1) { asm volatile("cp.async.wait_group 0;" ::: "memory"); }
        else                 { asm volatile("cp.async.wait_group 1;" ::: "memory"); }
        __syncthreads();
        if (kc + 2 < FC_NC) load_chunk(kc + 2, (kc + 2) % 3);
        uint32_t sa = sA + st * GBUF_B + aBase;
        uint32_t sbm = sB + st * GBUF_B + bBase;
        #pragma unroll
        for (int ks = 0; ks < 4; ks++) {
            uint32_t koff = (uint32_t)(ks * 16 * 2);
            uint32_t a0[4], a1[4];
            LDSM4(a0[0], a0[1], a0[2], a0[3], sa + koff);
            LDSM4(a1[0], a1[1], a1[2], a1[3], sa + 16 * GLDA * 2 + koff);
            uint32_t bf[16];
            #pragma unroll
            for (int nt = 0; nt < 4; nt++)
                LDSM4(bf[nt * 4 + 0], bf[nt * 4 + 1], bf[nt * 4 + 2], bf[nt * 4 + 3],
                      sbm + nt * 16 * GLDA * 2 + koff);
            #pragma unroll
            for (int j = 0; j < 8; j++) {
                int nt = j >> 1, hf = j & 1;
                MMA16816(acc[0][j], a0, bf[nt * 4 + hf * 2], bf[nt * 4 + hf * 2 + 1]);
                MMA16816(acc[1][j], a1, bf[nt * 4 + hf * 2], bf[nt * 4 + hf * 2 + 1]);
            }
        }
    }
    __syncthreads();

    float bv[8][2];
    #pragma unroll
    for (int j = 0; j < 8; j++) {
        int n = n0 + wn * 64 + j * 8 + (lane & 3) * 2;
        bv[j][0] = __ldg(bias + n);
        bv[j][1] = __ldg(bias + n + 1);
    }
    #pragma unroll
    for (int mt = 0; mt < 2; mt++) {
        #pragma unroll
        for (int half = 0; half < 2; half++) {
            int m = m0 + wm * 32 + mt * 16 + (lane >> 2) + half * 8;
            int t = m >> 5, b = m & 31;
            float* orow = out + (size_t)b * (TT * VV) + (size_t)t * VV;
            #pragma unroll
            for (int j = 0; j < 8; j++) {
                int n = n0 + wn * 64 + j * 8 + (lane & 3) * 2;
                float2 v;
                v.x = acc[mt][j][half * 2 + 0] + bv[j][0];
                v.y = acc[mt][j][half * 2 + 1] + bv[j][1];
                *(float2*)(orow + n) = v;
            }
        }
    }
}

// ---------------- launch ----------------
extern "C" void kernel_launch(void* const* d_in, const int* in_sizes, int n_in,
                              void* d_out, int out_size) {
    const int* src = (const int*)d_in[0];
    const int* tgt = (const int*)d_in[2];
    const float* enc_emb = (const float*)d_in[3];
    const float* enc_Wih = (const float*)d_in[4];
    const float* enc_Whh = (const float*)d_in[5];
    const float* enc_bih = (const float*)d_in[6];
    const float* enc_bhh = (const float*)d_in[7];
    const float* dec_emb = (const float*)d_in[8];
    const float* dec_Wih = (const float*)d_in[9];
    const float* dec_Whh = (const float*)d_in[10];
    const float* dec_bih = (const float*)d_in[11];
    const float* dec_bhh = (const float*)d_in[12];
    const float* fc_W = (const float*)d_in[13];
    const float* fc_b = (const float*)d_in[14];
    float* out = (float*)d_out;

    cudaFuncSetAttribute(fc_mma, cudaFuncAttributeMaxDynamicSharedMemorySize, MM_SMEM);
    cudaFuncSetAttribute(gi_mma, cudaFuncAttributeMaxDynamicSharedMemorySize, MM_SMEM);

    gatherX<<<SS * BB / 8, 256>>>(enc_emb, src, SS, 0);                 // 1
    splitWih<<<H3 / 8, 256>>>(enc_Wih, EE, 0);                          // 2
    gi_mma<<<dim3(SS * BB / GBM, H3 / GBN), 256, MM_SMEM>>>(enc_bih, 0);// 3
    enc_scan<<<NCTA, 512>>>(enc_Whh, enc_bhh);                          // 4 <- profiled
    gatherX<<<TT * BB / 8, 256>>>(dec_emb, tgt, TT, 1);                 // 5
    splitWih<<<H3 / 8, 256>>>(dec_Wih, EE + HH, 1);                     // 6
    gi_mma<<<dim3(TT * BB / GBM, H3 / GBN), 256, MM_SMEM>>>(dec_bih, 1);// 7
    dec_scan<<<NCTA, 512>>>(dec_Whh, dec_bhh, dec_Wih, src);            // 8
    convA<<<512, 1024>>>();                                             // 9
    convW<<<(VV * 256) / 1024, 1024>>>(fc_W);                           // 10
    fc_mma<<<dim3(TT * BB / GBM, VV / GBN), 256, MM_SMEM>>>(fc_b, out); // 11
}

// round 11
// speedup vs baseline: 1.3089x; 1.1885x over previous
#include <cuda_runtime.h>
#include <cuda_bf16.h>
#include <cstdint>

// Problem constants
#define BB 32
#define SS 256
#define TT 64
#define EE 256
#define HH 512
#define VV 32000
#define H3 1536

// GEMM tile config (both gi and fc): 128x128 tile, 256 thr, BK=64, 3-stage
#define GBM 128
#define GBN 128
#define GBK 64
#define GLDA 72                 // padded row (bf16 elems)
#define GBUF_B (GBM * GLDA * 2) // 18432 bytes per stage buffer
#define MM_SMEM (6 * GBUF_B)    // 110592 (3 stages x (A+B))

// K layouts (deduplicated): stored [hi | lo]
#define FCK 2048                // fc: pred/W rows
#define GIX 512                 // gi: emb/Wih rows
#define FC_NC 48                // 3 segments x 16 chunks
#define GI_NC 12                // 3 segments x 4 chunks

#define NCTA 128
#define DEC_WSMEM 49152         // dec weight smem (16 warps x 6 x 128 floats)

// ---------------- scratch ----------------
__device__ float g_enc_gi[SS * H3 * BB];
__device__ float g_dec_gie[TT * H3 * BB];
__device__ float g_eo[SS * HH * BB];
__device__ float g_h0[HH * BB];          // never written -> stays zero
__device__ float g_hdec[2][HH * BB];
__device__ float g_ctx[HH * BB];
__device__ float g_scores[SS * BB];
__device__ float g_pred[(TT * BB) * (2 * HH)];
__device__ __nv_bfloat16 g_Wb[(size_t)VV * FCK];        // [hi|lo] 131MB
__device__ __nv_bfloat16 g_Ab[(size_t)(TT * BB) * FCK]; // [hi|lo]
__device__ __nv_bfloat16 g_Xe[(size_t)(SS * BB) * GIX];
__device__ __nv_bfloat16 g_Xd[(size_t)(TT * BB) * GIX];
__device__ __nv_bfloat16 g_We[(size_t)H3 * GIX];
__device__ __nv_bfloat16 g_Wd[(size_t)H3 * GIX];
__device__ unsigned g_bar_cnt;
__device__ unsigned g_bar_gen;

// ---------------- grid barrier (proven Round-1 implementation) ----------------
__device__ __forceinline__ void grid_sync(unsigned nb) {
    __syncthreads();
    if (threadIdx.x == 0) {
        __threadfence();
        volatile unsigned* genp = &g_bar_gen;
        unsigned gen = *genp;
        if (atomicAdd(&g_bar_cnt, 1u) == nb - 1u) {
            g_bar_cnt = 0;
            __threadfence();
            *genp = gen + 1u;
        } else {
            while (*genp == gen) { }
            __threadfence();
        }
    }
    __syncthreads();
}

__device__ __forceinline__ float sigm(float x) { return 1.0f / (1.0f + __expf(-x)); }

__device__ __forceinline__ uint32_t smem_u32(const void* p) {
    uint32_t a;
    asm("{ .reg .u64 t; cvta.to.shared.u64 t, %1; cvt.u32.u64 %0, t; }" : "=r"(a) : "l"(p));
    return a;
}
__device__ __forceinline__ void cpasync16(uint32_t dst, const void* src) {
    asm volatile("cp.async.cg.shared.global [%0], [%1], 16;" :: "r"(dst), "l"(src) : "memory");
}
#define LDSM4(r0, r1, r2, r3, addr) \
    asm volatile("ldmatrix.sync.aligned.m8n8.x4.shared.b16 {%0,%1,%2,%3}, [%4];" \
                 : "=r"(r0), "=r"(r1), "=r"(r2), "=r"(r3) : "r"(addr))
#define MMA16816(c, a, b0, b1) \
    asm volatile("mma.sync.aligned.m16n8k16.row.col.f32.bf16.bf16.f32 " \
                 "{%0,%1,%2,%3}, {%4,%5,%6,%7}, {%8,%9}, {%0,%1,%2,%3};" \
                 : "+f"((c)[0]), "+f"((c)[1]), "+f"((c)[2]), "+f"((c)[3]) \
                 : "r"((a)[0]), "r"((a)[1]), "r"((a)[2]), "r"((a)[3]), "r"(b0), "r"(b1))

// split helpers
__device__ __forceinline__ void split4(float4 v, __nv_bfloat162& hA, __nv_bfloat162& hB,
                                       __nv_bfloat162& lA, __nv_bfloat162& lB) {
    __nv_bfloat16 h0 = __float2bfloat16(v.x), h1 = __float2bfloat16(v.y);
    __nv_bfloat16 h2 = __float2bfloat16(v.z), h3 = __float2bfloat16(v.w);
    __nv_bfloat16 l0 = __float2bfloat16(v.x - __bfloat162float(h0));
    __nv_bfloat16 l1 = __float2bfloat16(v.y - __bfloat162float(h1));
    __nv_bfloat16 l2 = __float2bfloat16(v.z - __bfloat162float(h2));
    __nv_bfloat16 l3 = __float2bfloat16(v.w - __bfloat162float(h3));
    hA = {h0, h1}; hB = {h2, h3}; lA = {l0, l1}; lB = {l2, l3};
}

// ---------------- W split: g_Wb[n] = [hi(1024) | lo(1024)]
__global__ void convW(const float* __restrict__ W) {
    size_t i = (size_t)blockIdx.x * 1024 + threadIdx.x;
    float4 v = ((const float4*)W)[i];
    size_t n = i >> 8;
    size_t k4 = (i & 255) * 4;
    __nv_bfloat162 hA, hB, lA, lB;
    split4(v, hA, hB, lA, lB);
    __nv_bfloat16* dst = g_Wb + n * FCK;
    *(__nv_bfloat162*)(dst + k4) = hA;          *(__nv_bfloat162*)(dst + k4 + 2) = hB;
    *(__nv_bfloat162*)(dst + 1024 + k4) = lA;   *(__nv_bfloat162*)(dst + 1024 + k4 + 2) = lB;
}

// ---------------- pred split: g_Ab[m] = [hi | lo]
__global__ void convA() {
    size_t i = (size_t)blockIdx.x * 1024 + threadIdx.x;
    float4 v = ((const float4*)g_pred)[i];
    size_t m = i >> 8;
    size_t k4 = (i & 255) * 4;
    __nv_bfloat162 hA, hB, lA, lB;
    split4(v, hA, hB, lA, lB);
    __nv_bfloat16* dst = g_Ab + m * FCK;
    *(__nv_bfloat162*)(dst + k4) = hA;          *(__nv_bfloat162*)(dst + k4 + 2) = hB;
    *(__nv_bfloat162*)(dst + 1024 + k4) = lA;   *(__nv_bfloat162*)(dst + 1024 + k4 + 2) = lB;
}

// ---------------- gather embedding rows + split: X[m] = [hi(256) | lo(256)]
__global__ void gatherX(const float* __restrict__ emb, const int* __restrict__ tok,
                        int L, int which) {
    __nv_bfloat16* X = which ? g_Xd : g_Xe;
    int m = blockIdx.x * 8 + (threadIdx.x >> 5);
    int lane = threadIdx.x & 31;
    int t = m >> 5, b = m & 31;
    int tv = tok[b * L + t];
    const float4* er = (const float4*)(emb + (size_t)tv * EE);
    __nv_bfloat16* dst = X + (size_t)m * GIX;
    #pragma unroll
    for (int q = 0; q < 2; q++) {
        float4 v = er[lane * 2 + q];
        int e = lane * 8 + q * 4;
        __nv_bfloat162 hA, hB, lA, lB;
        split4(v, hA, hB, lA, lB);
        *(__nv_bfloat162*)(dst + e) = hA;            *(__nv_bfloat162*)(dst + e + 2) = hB;
        *(__nv_bfloat162*)(dst + 256 + e) = lA;      *(__nv_bfloat162*)(dst + 256 + e + 2) = lB;
    }
}

// ---------------- split Wih rows (first 256 cols): out[j] = [hi | lo]
__global__ void splitWih(const float* __restrict__ W, int stride, int which) {
    __nv_bfloat16* out = which ? g_Wd : g_We;
    int j = blockIdx.x * 8 + (threadIdx.x >> 5);
    int lane = threadIdx.x & 31;
    const float4* wr = (const float4*)(W + (size_t)j * stride);
    __nv_bfloat16* dst = out + (size_t)j * GIX;
    #pragma unroll
    for (int q = 0; q < 2; q++) {
        float4 v = wr[lane * 2 + q];
        int e = lane * 8 + q * 4;
        __nv_bfloat162 hA, hB, lA, lB;
        split4(v, hA, hB, lA, lB);
        *(__nv_bfloat162*)(dst + e) = hA;            *(__nv_bfloat162*)(dst + e + 2) = hB;
        *(__nv_bfloat162*)(dst + 256 + e) = lA;      *(__nv_bfloat162*)(dst + 256 + e + 2) = lB;
    }
}

// ---------------- gi GEMM via HMMA (256 thr, 128x128, K eff 768)
__global__ void __launch_bounds__(256) gi_mma(const float* __restrict__ bih, int which) {
    extern __shared__ uint8_t dynsmem[];
    uint32_t sA = smem_u32(dynsmem);           // 3 stages
    uint32_t sB = sA + 3 * GBUF_B;

    const __nv_bfloat16* A = which ? g_Xd : g_Xe;
    const __nv_bfloat16* Bm = which ? g_Wd : g_We;
    float* outg = which ? g_dec_gie : g_enc_gi;

    int tid = threadIdx.x;
    int wid = tid >> 5, lane = tid & 31;
    int wm = wid & 3, wn = wid >> 2;
    int m0 = blockIdx.x * GBM;
    int n0 = blockIdx.y * GBN;

    const char* Ag = (const char*)(A + (size_t)m0 * GIX);
    const char* Bg = (const char*)(Bm + (size_t)n0 * GIX);
    int lrow = tid >> 3, lu = tid & 7;

    auto load_chunk = [&](int kc, int st) {
        int seg = kc >> 2, c = kc & 3;
        size_t aoff = (size_t)(((seg == 2) ? 256 : 0) + c * 64) * 2;   // bytes
        size_t boff = (size_t)(((seg == 1) ? 256 : 0) + c * 64) * 2;
        uint32_t sa = sA + st * GBUF_B;
        uint32_t sbm = sB + st * GBUF_B;
        #pragma unroll
        for (int it = 0; it < 4; it++) {
            int row = it * 32 + lrow;
            uint32_t doff = (uint32_t)(row * (GLDA * 2) + lu * 16);
            cpasync16(sa + doff, Ag + (size_t)row * (GIX * 2) + aoff + lu * 16);
            cpasync16(sbm + doff, Bg + (size_t)row * (GIX * 2) + boff + lu * 16);
        }
        asm volatile("cp.async.commit_group;" ::: "memory");
    };

    float acc[2][8][4];
    #pragma unroll
    for (int a = 0; a < 2; a++)
        #pragma unroll
        for (int b = 0; b < 8; b++)
            #pragma unroll
            for (int c = 0; c < 4; c++) acc[a][b][c] = 0.0f;

    uint32_t aBase = (uint32_t)(((wm * 32 + (lane & 15)) * GLDA + (lane >> 4) * 8) * 2);
    uint32_t bBase = (uint32_t)(((wn * 64 + (lane & 7) + ((lane >> 4) & 1) * 8) * GLDA
                                 + ((lane >> 3) & 1) * 8) * 2);

    load_chunk(0, 0);
    load_chunk(1, 1);
    for (int kc = 0; kc < GI_NC; kc++) {
        int st = kc % 3;
        if (kc == GI_NC - 1) { asm volatile("cp.async.wait_group 0;" ::: "memory"); }
        else                 { asm volatile("cp.async.wait_group 1;" ::: "memory"); }
        __syncthreads();
        if (kc + 2 < GI_NC) load_chunk(kc + 2, (kc + 2) % 3);
        uint32_t sa = sA + st * GBUF_B + aBase;
        uint32_t sbm = sB + st * GBUF_B + bBase;
        #pragma unroll
        for (int ks = 0; ks < 4; ks++) {
            uint32_t koff = (uint32_t)(ks * 16 * 2);
            uint32_t a0[4], a1[4];
            LDSM4(a0[0], a0[1], a0[2], a0[3], sa + koff);
            LDSM4(a1[0], a1[1], a1[2], a1[3], sa + 16 * GLDA * 2 + koff);
            uint32_t bf[16];
            #pragma unroll
            for (int nt = 0; nt < 4; nt++)
                LDSM4(bf[nt * 4 + 0], bf[nt * 4 + 1], bf[nt * 4 + 2], bf[nt * 4 + 3],
                      sbm + nt * 16 * GLDA * 2 + koff);
            #pragma unroll
            for (int j = 0; j < 8; j++) {
                int nt = j >> 1, hf = j & 1;
                MMA16816(acc[0][j], a0, bf[nt * 4 + hf * 2], bf[nt * 4 + hf * 2 + 1]);
                MMA16816(acc[1][j], a1, bf[nt * 4 + hf * 2], bf[nt * 4 + hf * 2 + 1]);
            }
        }
    }
    __syncthreads();

    #pragma unroll
    for (int mt = 0; mt < 2; mt++) {
        #pragma unroll
        for (int half = 0; half < 2; half++) {
            int m = m0 + wm * 32 + mt * 16 + (lane >> 2) + half * 8;
            int t = m >> 5, b = m & 31;
            float* obase = outg + (size_t)t * (H3 * BB) + b;
            #pragma unroll
            for (int j = 0; j < 8; j++) {
                int n = n0 + wn * 64 + j * 8 + (lane & 3) * 2;
                obase[(size_t)n * 32] = acc[mt][j][half * 2 + 0] + __ldg(bih + n);
                obase[(size_t)(n + 1) * 32] = acc[mt][j][half * 2 + 1] + __ldg(bih + n + 1);
            }
        }
    }
}

// ---------------- encoder scan (weights in SMEM, gi prefetched) ----------------
__global__ void __launch_bounds__(512) enc_scan(const float* __restrict__ Whh,
                                                const float* __restrict__ bhh) {
    int wid = threadIdx.x >> 5, lane = threadIdx.x & 31;
    int iLocal = wid & 3;
    int kq = wid >> 2;
    int i = blockIdx.x * 4 + iLocal;
    __shared__ float sW[16][3][128];       // loop-invariant weights (24KB)
    __shared__ float ps[4][3][3][32];
    __shared__ float sgi[2][12][32];       // double-buffered gi prefetch
    __shared__ float sbh[12];

    // one-time weight load: warp (iLocal,kq) owns rows (g*HH+i), cols kq*128..+127
    #pragma unroll
    for (int g = 0; g < 3; g++) {
        float4 w = *(const float4*)(Whh + ((size_t)g * HH + i) * HH + kq * 128 + lane * 4);
        *(float4*)&sW[wid][g][lane * 4] = w;
    }
    if (threadIdx.x < 12) {
        int g = threadIdx.x >> 2, il = threadIdx.x & 3;
        sbh[threadIdx.x] = bhh[g * HH + blockIdx.x * 4 + il];
    }

    auto prefetch_gi = [&](int t, int buf) {
        if (threadIdx.x < 96) {
            int row = threadIdx.x >> 3, u = threadIdx.x & 7;   // row = g*4+il
            int g = row >> 2, il = row & 3;
            const float* src = g_enc_gi + (size_t)t * (H3 * BB)
                             + ((size_t)g * HH + blockIdx.x * 4 + il) * 32 + u * 4;
            cpasync16(smem_u32(&sgi[buf][row][u * 4]), src);
        }
        asm volatile("cp.async.commit_group;" ::: "memory");
    };
    prefetch_gi(0, 0);
    __syncthreads();   // sW + sbh ready

    for (int t = 0; t < SS; t++) {
        if (t + 1 < SS) prefetch_gi(t + 1, (t + 1) & 1);
        const float* hprev = t ? (g_eo + (t - 1) * (HH * BB)) : g_h0;
        const float* hp = hprev + kq * 128 * 32 + lane;
        float s0 = 0, s1 = 0, s2 = 0;
        #pragma unroll 8
        for (int q = 0; q < 32; q++) {
            float h0 = hp[q * 128 + 0];
            float h1 = hp[q * 128 + 32];
            float h2 = hp[q * 128 + 64];
            float h3 = hp[q * 128 + 96];
            float4 w0 = *(const float4*)&sW[wid][0][q * 4];
            float4 w1 = *(const float4*)&sW[wid][1][q * 4];
            float4 w2 = *(const float4*)&sW[wid][2][q * 4];
            s0 += w0.x * h0 + w0.y * h1 + w0.z * h2 + w0.w * h3;
            s1 += w1.x * h0 + w1.y * h1 + w1.z * h2 + w1.w * h3;
            s2 += w2.x * h0 + w2.y * h1 + w2.z * h2 + w2.w * h3;
        }
        if (kq > 0) {
            ps[iLocal][kq - 1][0][lane] = s0;
            ps[iLocal][kq - 1][1][lane] = s1;
            ps[iLocal][kq - 1][2][lane] = s2;
        }
        asm volatile("cp.async.wait_group 1;" ::: "memory");
        __syncthreads();
        if (wid < 4) {
            float rh = s0 + ps[wid][0][0][lane] + ps[wid][1][0][lane] + ps[wid][2][0][lane] + sbh[wid];
            float zh = s1 + ps[wid][0][1][lane] + ps[wid][1][1][lane] + ps[wid][2][1][lane] + sbh[4 + wid];
            float nh = s2 + ps[wid][0][2][lane] + ps[wid][1][2][lane] + ps[wid][2][2][lane] + sbh[8 + wid];
            float ir = sgi[t & 1][wid][lane];
            float iz = sgi[t & 1][4 + wid][lane];
            float in_ = sgi[t & 1][8 + wid][lane];
            float r = sigm(ir + rh);
            float z = sigm(iz + zh);
            float n = tanhf(in_ + r * nh);
            int ii = blockIdx.x * 4 + wid;
            float hv = hprev[ii * 32 + lane];
            g_eo[t * (HH * BB) + ii * 32 + lane] = (1.0f - z) * n + z * hv;
        }
        grid_sync(gridDim.x);
    }
}

// ---------------- decoder scan (phase-D weights in dynamic SMEM, gie prefetched)
__global__ void __launch_bounds__(512) dec_scan(const float* __restrict__ Whh,
                                                const float* __restrict__ bhh,
                                                const float* __restrict__ Wih,
                                                const int* __restrict__ src) {
    extern __shared__ float sWD[];         // [wid][6][128] = 48KB
    int wid = threadIdx.x >> 5, lane = threadIdx.x & 31;
    int iLocal = wid & 3;
    int kqD = wid >> 2;
    int iD = blockIdx.x * 4 + iLocal;
    __shared__ float psA[2][8][32];
    __shared__ float psC[4][4][32];
    __shared__ float denS[32];
    __shared__ float psD[4][3][6][32];
    __shared__ float sgie[12][32];
    __shared__ float sbh[12];

    // one-time weight load: 6 matrices per warp (3 Whh rows, 3 Wih ctx rows)
    float* wrow = sWD + wid * 6 * 128;
    #pragma unroll
    for (int g = 0; g < 3; g++) {
        *(float4*)&wrow[g * 128 + lane * 4] =
            *(const float4*)(Whh + ((size_t)g * HH + iD) * HH + kqD * 128 + lane * 4);
        *(float4*)&wrow[(3 + g) * 128 + lane * 4] =
            *(const float4*)(Wih + ((size_t)g * HH + iD) * 768 + EE + kqD * 128 + lane * 4);
    }
    if (threadIdx.x < 12) {
        int g = threadIdx.x >> 2, il = threadIdx.x & 3;
        sbh[threadIdx.x] = bhh[g * HH + blockIdx.x * 4 + il];
    }
    __syncthreads();

    for (int t = 0; t < TT; t++) {
        // prefetch gie[t] (consumed in phase D of this step)
        if (threadIdx.x < 96) {
            int row = threadIdx.x >> 3, u = threadIdx.x & 7;
            int g = row >> 2, il = row & 3;
            const float* srcp = g_dec_gie + (size_t)t * (H3 * BB)
                              + ((size_t)g * HH + blockIdx.x * 4 + il) * 32 + u * 4;
            cpasync16(smem_u32(&sgie[row][u * 4]), srcp);
        }
        asm volatile("cp.async.commit_group;" ::: "memory");

        const float* h = t ? g_hdec[t & 1] : (g_eo + (SS - 1) * (HH * BB));
        {
            int s = blockIdx.x * 2 + (wid & 1);
            int kq8 = wid >> 1;
            float acc = 0.0f;
            const float* eo = g_eo + s * (HH * BB) + kq8 * 64 * 32 + lane;
            const float* hp = h + kq8 * 64 * 32 + lane;
            #pragma unroll 8
            for (int k = 0; k < 64; k++) acc += eo[k * 32] * hp[k * 32];
            psA[wid & 1][kq8][lane] = acc;
            __syncthreads();
            if (wid < 2) {
                int ss2 = blockIdx.x * 2 + wid;
                float sc = 0.0f;
                #pragma unroll
                for (int q = 0; q < 8; q++) sc += psA[wid][q][lane];
                int tokv = src[lane * SS + ss2];
                float e = (tokv == 0) ? 0.0f : __expf(sc);
                g_scores[ss2 * 32 + lane] = e;
            }
        }
        grid_sync(gridDim.x);
        {
            int k = blockIdx.x * 4 + (wid & 3);
            int sq = wid >> 2;
            float acc = 0.0f;
            const float* eo = g_eo + sq * 64 * (HH * BB) + k * 32 + lane;
            const float* sce = g_scores + sq * 64 * 32 + lane;
            #pragma unroll 8
            for (int s = 0; s < 64; s++) acc += sce[s * 32] * eo[s * (HH * BB)];
            psC[wid & 3][sq][lane] = acc;
            if (wid == 0) {
                float d = 0.0f;
                const float* sp = g_scores + lane;
                #pragma unroll 8
                for (int s = 0; s < SS; s++) d += sp[s * 32];
                denS[lane] = d;
            }
            __syncthreads();
            if (wid < 4) {
                int kk = blockIdx.x * 4 + wid;
                float c = (psC[wid][0][lane] + psC[wid][1][lane] + psC[wid][2][lane] + psC[wid][3][lane])
                          / denS[lane];
                g_ctx[kk * 32 + lane] = c;
                g_pred[(t * 32 + lane) * (2 * HH) + HH + kk] = c;
            }
        }
        grid_sync(gridDim.x);
        {
            float a0 = 0, a1 = 0, a2 = 0, c0 = 0, c1 = 0, c2 = 0;
            {
                const float* hp = h + kqD * 128 * 32 + lane;
                const float* cp = g_ctx + kqD * 128 * 32 + lane;
                #pragma unroll 4
                for (int q = 0; q < 32; q++) {
                    float h0 = hp[q * 128 + 0], h1 = hp[q * 128 + 32];
                    float h2 = hp[q * 128 + 64], h3 = hp[q * 128 + 96];
                    float x0 = cp[q * 128 + 0], x1 = cp[q * 128 + 32];
                    float x2 = cp[q * 128 + 64], x3 = cp[q * 128 + 96];
                    float4 w;
                    w = *(const float4*)&wrow[0 * 128 + q * 4];
                    a0 += w.x * h0 + w.y * h1 + w.z * h2 + w.w * h3;
                    w = *(const float4*)&wrow[1 * 128 + q * 4];
                    a1 += w.x * h0 + w.y * h1 + w.z * h2 + w.w * h3;
                    w = *(const float4*)&wrow[2 * 128 + q * 4];
                    a2 += w.x * h0 + w.y * h1 + w.z * h2 + w.w * h3;
                    w = *(const float4*)&wrow[3 * 128 + q * 4];
                    c0 += w.x * x0 + w.y * x1 + w.z * x2 + w.w * x3;
                    w = *(const float4*)&wrow[4 * 128 + q * 4];
                    c1 += w.x * x0 + w.y * x1 + w.z * x2 + w.w * x3;
                    w = *(const float4*)&wrow[5 * 128 + q * 4];
                    c2 += w.x * x0 + w.y * x1 + w.z * x2 + w.w * x3;
                }
            }
            if (kqD > 0) {
                psD[iLocal][kqD - 1][0][lane] = a0;
                psD[iLocal][kqD - 1][1][lane] = a1;
                psD[iLocal][kqD - 1][2][lane] = a2;
                psD[iLocal][kqD - 1][3][lane] = c0;
                psD[iLocal][kqD - 1][4][lane] = c1;
                psD[iLocal][kqD - 1][5][lane] = c2;
            }
            asm volatile("cp.async.wait_group 0;" ::: "memory");
            __syncthreads();
            if (wid < 4) {
                float rh = a0, zh = a1, nh = a2, rc = c0, zc = c1, nc = c2;
                #pragma unroll
                for (int kk = 0; kk < 3; kk++) {
                    rh += psD[wid][kk][0][lane];
                    zh += psD[wid][kk][1][lane];
                    nh += psD[wid][kk][2][lane];
                    rc += psD[wid][kk][3][lane];
                    zc += psD[wid][kk][4][lane];
                    nc += psD[wid][kk][5][lane];
                }
                rh += sbh[wid]; zh += sbh[4 + wid]; nh += sbh[8 + wid];
                float ir = sgie[wid][lane] + rc;
                float iz = sgie[4 + wid][lane] + zc;
                float in_ = sgie[8 + wid][lane] + nc;
                float r = sigm(ir + rh);
                float z = sigm(iz + zh);
                float n = tanhf(in_ + r * nh);
                int ii = blockIdx.x * 4 + wid;
                float hold = h[ii * 32 + lane];
                float hn = (1.0f - z) * n + z * hold;
                g_hdec[(t + 1) & 1][ii * 32 + lane] = hn;
                g_pred[(t * 32 + lane) * (2 * HH) + ii] = hn;
            }
        }
        grid_sync(gridDim.x);
    }
}

// ---------------- fc GEMM via mma.sync (256 thr, 128x128, K eff 3072) ----------
__global__ void __launch_bounds__(256) fc_mma(const float* __restrict__ bias,
                                              float* __restrict__ out) {
    extern __shared__ uint8_t dynsmem[];
    uint32_t sA = smem_u32(dynsmem);           // 3 stages
    uint32_t sB = sA + 3 * GBUF_B;

    int tid = threadIdx.x;
    int wid = tid >> 5, lane = tid & 31;
    int wm = wid & 3, wn = wid >> 2;
    int m0 = blockIdx.x * GBM;
    int n0 = blockIdx.y * GBN;

    const char* Ag = (const char*)(g_Ab + (size_t)m0 * FCK);
    const char* Bg = (const char*)(g_Wb + (size_t)n0 * FCK);
    int lrow = tid >> 3, lu = tid & 7;

    auto load_chunk = [&](int kc, int st) {
        int seg = kc >> 4, c = kc & 15;
        size_t aoff = (size_t)(((seg == 2) ? 1024 : 0) + c * 64) * 2;   // bytes
        size_t boff = (size_t)(((seg == 1) ? 1024 : 0) + c * 64) * 2;
        uint32_t sa = sA + st * GBUF_B;
        uint32_t sbm = sB + st * GBUF_B;
        #pragma unroll
        for (int it = 0; it < 4; it++) {
            int row = it * 32 + lrow;
            uint32_t doff = (uint32_t)(row * (GLDA * 2) + lu * 16);
            cpasync16(sa + doff, Ag + (size_t)row * (FCK * 2) + aoff + lu * 16);
            cpasync16(sbm + doff, Bg + (size_t)row * (FCK * 2) + boff + lu * 16);
        }
        asm volatile("cp.async.commit_group;" ::: "memory");
    };

    float acc[2][8][4];
    #pragma unroll
    for (int a = 0; a < 2; a++)
        #pragma unroll
        for (int b = 0; b < 8; b++)
            #pragma unroll
            for (int c = 0; c < 4; c++) acc[a][b][c] = 0.0f;

    uint32_t aBase = (uint32_t)(((wm * 32 + (lane & 15)) * GLDA + (lane >> 4) * 8) * 2);
    uint32_t bBase = (uint32_t)(((wn * 64 + (lane & 7) + ((lane >> 4) & 1) * 8) * GLDA
                                 + ((lane >> 3) & 1) * 8) * 2);

    load_chunk(0, 0);
    load_chunk(1, 1);
    for (int kc = 0; kc < FC_NC; kc++) {
        int st = kc % 3;
        if (kc == FC_NC - 1) { asm volatile("cp.async.wait_group 0;" ::: "memory"); }
        else                 { asm volatile("cp.async.wait_group 1;" ::: "memory"); }
        __syncthreads();
        if (kc + 2 < FC_NC) load_chunk(kc + 2, (kc + 2) % 3);
        uint32_t sa = sA + st * GBUF_B + aBase;
        uint32_t sbm = sB + st * GBUF_B + bBase;
        #pragma unroll
        for (int ks = 0; ks < 4; ks++) {
            uint32_t koff = (uint32_t)(ks * 16 * 2);
            uint32_t a0[4], a1[4];
            LDSM4(a0[0], a0[1], a0[2], a0[3], sa + koff);
            LDSM4(a1[0], a1[1], a1[2], a1[3], sa + 16 * GLDA * 2 + koff);
            uint32_t bf[16];
            #pragma unroll
            for (int nt = 0; nt < 4; nt++)
                LDSM4(bf[nt * 4 + 0], bf[nt * 4 + 1], bf[nt * 4 + 2], bf[nt * 4 + 3],
                      sbm + nt * 16 * GLDA * 2 + koff);
            #pragma unroll
            for (int j = 0; j < 8; j++) {
                int nt = j >> 1, hf = j & 1;
                MMA16816(acc[0][j], a0, bf[nt * 4 + hf * 2], bf[nt * 4 + hf * 2 + 1]);
                MMA16816(acc[1][j], a1, bf[nt * 4 + hf * 2], bf[nt * 4 + hf * 2 + 1]);
            }
        }
    }
    __syncthreads();

    float bv[8][2];
    #pragma unroll
    for (int j = 0; j < 8; j++) {
        int n = n0 + wn * 64 + j * 8 + (lane & 3) * 2;
        bv[j][0] = __ldg(bias + n);
        bv[j][1] = __ldg(bias + n + 1);
    }
    #pragma unroll
    for (int mt = 0; mt < 2; mt++) {
        #pragma unroll
        for (int half = 0; half < 2; half++) {
            int m = m0 + wm * 32 + mt * 16 + (lane >> 2) + half * 8;
            int t = m >> 5, b = m & 31;
            float* orow = out + (size_t)b * (TT * VV) + (size_t)t * VV;
            #pragma unroll
            for (int j = 0; j < 8; j++) {
                int n = n0 + wn * 64 + j * 8 + (lane & 3) * 2;
                float2 v;
                v.x = acc[mt][j][half * 2 + 0] + bv[j][0];
                v.y = acc[mt][j][half * 2 + 1] + bv[j][1];
                *(float2*)(orow + n) = v;
            }
        }
    }
}

// ---------------- launch ----------------
extern "C" void kernel_launch(void* const* d_in, const int* in_sizes, int n_in,
                              void* d_out, int out_size) {
    const int* src = (const int*)d_in[0];
    const int* tgt = (const int*)d_in[2];
    const float* enc_emb = (const float*)d_in[3];
    const float* enc_Wih = (const float*)d_in[4];
    const float* enc_Whh = (const float*)d_in[5];
    const float* enc_bih = (const float*)d_in[6];
    const float* enc_bhh = (const float*)d_in[7];
    const float* dec_emb = (const float*)d_in[8];
    const float* dec_Wih = (const float*)d_in[9];
    const float* dec_Whh = (const float*)d_in[10];
    const float* dec_bih = (const float*)d_in[11];
    const float* dec_bhh = (const float*)d_in[12];
    const float* fc_W = (const float*)d_in[13];
    const float* fc_b = (const float*)d_in[14];
    float* out = (float*)d_out;

    cudaFuncSetAttribute(fc_mma, cudaFuncAttributeMaxDynamicSharedMemorySize, MM_SMEM);
    cudaFuncSetAttribute(gi_mma, cudaFuncAttributeMaxDynamicSharedMemorySize, MM_SMEM);
    cudaFuncSetAttribute(dec_scan, cudaFuncAttributeMaxDynamicSharedMemorySize, DEC_WSMEM);

    gatherX<<<SS * BB / 8, 256>>>(enc_emb, src, SS, 0);                 // 1
    splitWih<<<H3 / 8, 256>>>(enc_Wih, EE, 0);                          // 2
    gi_mma<<<dim3(SS * BB / GBM, H3 / GBN), 256, MM_SMEM>>>(enc_bih, 0);// 3
    enc_scan<<<NCTA, 512>>>(enc_Whh, enc_bhh);                          // 4 <- profiled
    gatherX<<<TT * BB / 8, 256>>>(dec_emb, tgt, TT, 1);                 // 5
    splitWih<<<H3 / 8, 256>>>(dec_Wih, EE + HH, 1);                     // 6
    gi_mma<<<dim3(TT * BB / GBM, H3 / GBN), 256, MM_SMEM>>>(dec_bih, 1);// 7
    dec_scan<<<NCTA, 512, DEC_WSMEM>>>(dec_Whh, dec_bhh, dec_Wih, src); // 8
    convA<<<512, 1024>>>();                                             // 9
    convW<<<(VV * 256) / 1024, 1024>>>(fc_W);                           // 10
    fc_mma<<<dim3(TT * BB / GBM, VV / GBN), 256, MM_SMEM>>>(fc_b, out); // 11
}

// round 12
// speedup vs baseline: 1.3150x; 1.0047x over previous
#include <cuda_runtime.h>
#include <cuda_bf16.h>
#include <cstdint>

// Problem constants
#define BB 32
#define SS 256
#define TT 64
#define EE 256
#define HH 512
#define VV 32000
#define H3 1536

// GEMM tile config (both gi and fc): 128x128 tile, 256 thr, BK=64, 3-stage
#define GBM 128
#define GBN 128
#define GBK 64
#define GLDA 72                 // padded row (bf16 elems)
#define GBUF_B (GBM * GLDA * 2) // 18432 bytes per stage buffer
#define MM_SMEM (6 * GBUF_B)    // 110592 (3 stages x (A+B))

// K layouts (deduplicated): stored [hi | lo]
#define FCK 2048                // fc: pred/W rows
#define GIX 512                 // gi: emb/Wih rows
#define FC_NC 48                // 3 segments x 16 chunks
#define GI_NC 12                // 3 segments x 4 chunks

#define NCTA 128
#define DEC_WSMEM 49152         // dec weight smem (16 warps x 6 x 128 floats)

// ---------------- scratch ----------------
__device__ float g_enc_gi[SS * H3 * BB];
__device__ float g_dec_gie[TT * H3 * BB];
__device__ float g_eo[SS * HH * BB];
__device__ float g_h0[HH * BB];          // never written -> stays zero
__device__ float g_hdec[2][HH * BB];
__device__ float g_ctx[HH * BB];
__device__ float g_scores[SS * BB];
__device__ float g_pred[(TT * BB) * (2 * HH)];
__device__ __nv_bfloat16 g_Wb[(size_t)VV * FCK];        // [hi|lo] 131MB
__device__ __nv_bfloat16 g_Ab[(size_t)(TT * BB) * FCK]; // [hi|lo]
__device__ __nv_bfloat16 g_Xe[(size_t)(SS * BB) * GIX];
__device__ __nv_bfloat16 g_Xd[(size_t)(TT * BB) * GIX];
__device__ __nv_bfloat16 g_We[(size_t)H3 * GIX];
__device__ __nv_bfloat16 g_Wd[(size_t)H3 * GIX];
__device__ unsigned g_bar_cnt;
__device__ unsigned g_bar_gen;

// ---------------- grid barrier (proven Round-1 implementation) ----------------
__device__ __forceinline__ void grid_sync(unsigned nb) {
    __syncthreads();
    if (threadIdx.x == 0) {
        __threadfence();
        volatile unsigned* genp = &g_bar_gen;
        unsigned gen = *genp;
        if (atomicAdd(&g_bar_cnt, 1u) == nb - 1u) {
            g_bar_cnt = 0;
            __threadfence();
            *genp = gen + 1u;
        } else {
            while (*genp == gen) { }
            __threadfence();
        }
    }
    __syncthreads();
}

__device__ __forceinline__ float sigm(float x) { return 1.0f / (1.0f + __expf(-x)); }

__device__ __forceinline__ uint32_t smem_u32(const void* p) {
    uint32_t a;
    asm("{ .reg .u64 t; cvta.to.shared.u64 t, %1; cvt.u32.u64 %0, t; }" : "=r"(a) : "l"(p));
    return a;
}
__device__ __forceinline__ void cpasync16(uint32_t dst, const void* src) {
    asm volatile("cp.async.cg.shared.global [%0], [%1], 16;" :: "r"(dst), "l"(src) : "memory");
}
#define LDSM4(r0, r1, r2, r3, addr) \
    asm volatile("ldmatrix.sync.aligned.m8n8.x4.shared.b16 {%0,%1,%2,%3}, [%4];" \
                 : "=r"(r0), "=r"(r1), "=r"(r2), "=r"(r3) : "r"(addr))
#define MMA16816(c, a, b0, b1) \
    asm volatile("mma.sync.aligned.m16n8k16.row.col.f32.bf16.bf16.f32 " \
                 "{%0,%1,%2,%3}, {%4,%5,%6,%7}, {%8,%9}, {%0,%1,%2,%3};" \
                 : "+f"((c)[0]), "+f"((c)[1]), "+f"((c)[2]), "+f"((c)[3]) \
                 : "r"((a)[0]), "r"((a)[1]), "r"((a)[2]), "r"((a)[3]), "r"(b0), "r"(b1))

// split helpers
__device__ __forceinline__ void split4(float4 v, __nv_bfloat162& hA, __nv_bfloat162& hB,
                                       __nv_bfloat162& lA, __nv_bfloat162& lB) {
    __nv_bfloat16 h0 = __float2bfloat16(v.x), h1 = __float2bfloat16(v.y);
    __nv_bfloat16 h2 = __float2bfloat16(v.z), h3 = __float2bfloat16(v.w);
    __nv_bfloat16 l0 = __float2bfloat16(v.x - __bfloat162float(h0));
    __nv_bfloat16 l1 = __float2bfloat16(v.y - __bfloat162float(h1));
    __nv_bfloat16 l2 = __float2bfloat16(v.z - __bfloat162float(h2));
    __nv_bfloat16 l3 = __float2bfloat16(v.w - __bfloat162float(h3));
    hA = {h0, h1}; hB = {h2, h3}; lA = {l0, l1}; lB = {l2, l3};
}

// ---------------- W split: g_Wb[n] = [hi(1024) | lo(1024)]
__global__ void convW(const float* __restrict__ W) {
    size_t i = (size_t)blockIdx.x * 1024 + threadIdx.x;
    float4 v = ((const float4*)W)[i];
    size_t n = i >> 8;
    size_t k4 = (i & 255) * 4;
    __nv_bfloat162 hA, hB, lA, lB;
    split4(v, hA, hB, lA, lB);
    __nv_bfloat16* dst = g_Wb + n * FCK;
    *(__nv_bfloat162*)(dst + k4) = hA;          *(__nv_bfloat162*)(dst + k4 + 2) = hB;
    *(__nv_bfloat162*)(dst + 1024 + k4) = lA;   *(__nv_bfloat162*)(dst + 1024 + k4 + 2) = lB;
}

// ---------------- pred split: g_Ab[m] = [hi | lo]
__global__ void convA() {
    size_t i = (size_t)blockIdx.x * 1024 + threadIdx.x;
    float4 v = ((const float4*)g_pred)[i];
    size_t m = i >> 8;
    size_t k4 = (i & 255) * 4;
    __nv_bfloat162 hA, hB, lA, lB;
    split4(v, hA, hB, lA, lB);
    __nv_bfloat16* dst = g_Ab + m * FCK;
    *(__nv_bfloat162*)(dst + k4) = hA;          *(__nv_bfloat162*)(dst + k4 + 2) = hB;
    *(__nv_bfloat162*)(dst + 1024 + k4) = lA;   *(__nv_bfloat162*)(dst + 1024 + k4 + 2) = lB;
}

// ---------------- gather embedding rows + split: X[m] = [hi(256) | lo(256)]
__global__ void gatherX(const float* __restrict__ emb, const int* __restrict__ tok,
                        int L, int which) {
    __nv_bfloat16* X = which ? g_Xd : g_Xe;
    int m = blockIdx.x * 8 + (threadIdx.x >> 5);
    int lane = threadIdx.x & 31;
    int t = m >> 5, b = m & 31;
    int tv = tok[b * L + t];
    const float4* er = (const float4*)(emb + (size_t)tv * EE);
    __nv_bfloat16* dst = X + (size_t)m * GIX;
    #pragma unroll
    for (int q = 0; q < 2; q++) {
        float4 v = er[lane * 2 + q];
        int e = lane * 8 + q * 4;
        __nv_bfloat162 hA, hB, lA, lB;
        split4(v, hA, hB, lA, lB);
        *(__nv_bfloat162*)(dst + e) = hA;            *(__nv_bfloat162*)(dst + e + 2) = hB;
        *(__nv_bfloat162*)(dst + 256 + e) = lA;      *(__nv_bfloat162*)(dst + 256 + e + 2) = lB;
    }
}

// ---------------- split Wih rows (first 256 cols): out[j] = [hi | lo]
__global__ void splitWih(const float* __restrict__ W, int stride, int which) {
    __nv_bfloat16* out = which ? g_Wd : g_We;
    int j = blockIdx.x * 8 + (threadIdx.x >> 5);
    int lane = threadIdx.x & 31;
    const float4* wr = (const float4*)(W + (size_t)j * stride);
    __nv_bfloat16* dst = out + (size_t)j * GIX;
    #pragma unroll
    for (int q = 0; q < 2; q++) {
        float4 v = wr[lane * 2 + q];
        int e = lane * 8 + q * 4;
        __nv_bfloat162 hA, hB, lA, lB;
        split4(v, hA, hB, lA, lB);
        *(__nv_bfloat162*)(dst + e) = hA;            *(__nv_bfloat162*)(dst + e + 2) = hB;
        *(__nv_bfloat162*)(dst + 256 + e) = lA;      *(__nv_bfloat162*)(dst + 256 + e + 2) = lB;
    }
}

// ---------------- gi GEMM via HMMA (256 thr, 128x128, K eff 768)
__global__ void __launch_bounds__(256) gi_mma(const float* __restrict__ bih, int which) {
    extern __shared__ uint8_t dynsmem[];
    uint32_t sA = smem_u32(dynsmem);           // 3 stages
    uint32_t sB = sA + 3 * GBUF_B;

    const __nv_bfloat16* A = which ? g_Xd : g_Xe;
    const __nv_bfloat16* Bm = which ? g_Wd : g_We;
    float* outg = which ? g_dec_gie : g_enc_gi;

    int tid = threadIdx.x;
    int wid = tid >> 5, lane = tid & 31;
    int wm = wid & 3, wn = wid >> 2;
    int m0 = blockIdx.x * GBM;
    int n0 = blockIdx.y * GBN;

    const char* Ag = (const char*)(A + (size_t)m0 * GIX);
    const char* Bg = (const char*)(Bm + (size_t)n0 * GIX);
    int lrow = tid >> 3, lu = tid & 7;

    auto load_chunk = [&](int kc, int st) {
        int seg = kc >> 2, c = kc & 3;
        size_t aoff = (size_t)(((seg == 2) ? 256 : 0) + c * 64) * 2;   // bytes
        size_t boff = (size_t)(((seg == 1) ? 256 : 0) + c * 64) * 2;
        uint32_t sa = sA + st * GBUF_B;
        uint32_t sbm = sB + st * GBUF_B;
        #pragma unroll
        for (int it = 0; it < 4; it++) {
            int row = it * 32 + lrow;
            uint32_t doff = (uint32_t)(row * (GLDA * 2) + lu * 16);
            cpasync16(sa + doff, Ag + (size_t)row * (GIX * 2) + aoff + lu * 16);
            cpasync16(sbm + doff, Bg + (size_t)row * (GIX * 2) + boff + lu * 16);
        }
        asm volatile("cp.async.commit_group;" ::: "memory");
    };

    float acc[2][8][4];
    #pragma unroll
    for (int a = 0; a < 2; a++)
        #pragma unroll
        for (int b = 0; b < 8; b++)
            #pragma unroll
            for (int c = 0; c < 4; c++) acc[a][b][c] = 0.0f;

    uint32_t aBase = (uint32_t)(((wm * 32 + (lane & 15)) * GLDA + (lane >> 4) * 8) * 2);
    uint32_t bBase = (uint32_t)(((wn * 64 + (lane & 7) + ((lane >> 4) & 1) * 8) * GLDA
                                 + ((lane >> 3) & 1) * 8) * 2);

    load_chunk(0, 0);
    load_chunk(1, 1);
    for (int kc = 0; kc < GI_NC; kc++) {
        int st = kc % 3;
        if (kc == GI_NC - 1) { asm volatile("cp.async.wait_group 0;" ::: "memory"); }
        else                 { asm volatile("cp.async.wait_group 1;" ::: "memory"); }
        __syncthreads();
        if (kc + 2 < GI_NC) load_chunk(kc + 2, (kc + 2) % 3);
        uint32_t sa = sA + st * GBUF_B + aBase;
        uint32_t sbm = sB + st * GBUF_B + bBase;
        #pragma unroll
        for (int ks = 0; ks < 4; ks++) {
            uint32_t koff = (uint32_t)(ks * 16 * 2);
            uint32_t a0[4], a1[4];
            LDSM4(a0[0], a0[1], a0[2], a0[3], sa + koff);
            LDSM4(a1[0], a1[1], a1[2], a1[3], sa + 16 * GLDA * 2 + koff);
            uint32_t bf[16];
            #pragma unroll
            for (int nt = 0; nt < 4; nt++)
                LDSM4(bf[nt * 4 + 0], bf[nt * 4 + 1], bf[nt * 4 + 2], bf[nt * 4 + 3],
                      sbm + nt * 16 * GLDA * 2 + koff);
            #pragma unroll
            for (int j = 0; j < 8; j++) {
                int nt = j >> 1, hf = j & 1;
                MMA16816(acc[0][j], a0, bf[nt * 4 + hf * 2], bf[nt * 4 + hf * 2 + 1]);
                MMA16816(acc[1][j], a1, bf[nt * 4 + hf * 2], bf[nt * 4 + hf * 2 + 1]);
            }
        }
    }
    __syncthreads();

    #pragma unroll
    for (int mt = 0; mt < 2; mt++) {
        #pragma unroll
        for (int half = 0; half < 2; half++) {
            int m = m0 + wm * 32 + mt * 16 + (lane >> 2) + half * 8;
            int t = m >> 5, b = m & 31;
            float* obase = outg + (size_t)t * (H3 * BB) + b;
            #pragma unroll
            for (int j = 0; j < 8; j++) {
                int n = n0 + wn * 64 + j * 8 + (lane & 3) * 2;
                obase[(size_t)n * 32] = acc[mt][j][half * 2 + 0] + __ldg(bih + n);
                obase[(size_t)(n + 1) * 32] = acc[mt][j][half * 2 + 1] + __ldg(bih + n + 1);
            }
        }
    }
}

// ---------------- encoder scan (weights in SMEM, gi prefetched) ----------------
__global__ void __launch_bounds__(512) enc_scan(const float* __restrict__ Whh,
                                                const float* __restrict__ bhh) {
    int wid = threadIdx.x >> 5, lane = threadIdx.x & 31;
    int iLocal = wid & 3;
    int kq = wid >> 2;
    int i = blockIdx.x * 4 + iLocal;
    __shared__ float sW[16][3][128];       // loop-invariant weights (24KB)
    __shared__ float ps[4][3][3][32];
    __shared__ float sgi[2][12][32];       // double-buffered gi prefetch
    __shared__ float sbh[12];

    // one-time weight load: warp (iLocal,kq) owns rows (g*HH+i), cols kq*128..+127
    #pragma unroll
    for (int g = 0; g < 3; g++) {
        float4 w = *(const float4*)(Whh + ((size_t)g * HH + i) * HH + kq * 128 + lane * 4);
        *(float4*)&sW[wid][g][lane * 4] = w;
    }
    if (threadIdx.x < 12) {
        int g = threadIdx.x >> 2, il = threadIdx.x & 3;
        sbh[threadIdx.x] = bhh[g * HH + blockIdx.x * 4 + il];
    }

    auto prefetch_gi = [&](int t, int buf) {
        if (threadIdx.x < 96) {
            int row = threadIdx.x >> 3, u = threadIdx.x & 7;   // row = g*4+il
            int g = row >> 2, il = row & 3;
            const float* src = g_enc_gi + (size_t)t * (H3 * BB)
                             + ((size_t)g * HH + blockIdx.x * 4 + il) * 32 + u * 4;
            cpasync16(smem_u32(&sgi[buf][row][u * 4]), src);
        }
        asm volatile("cp.async.commit_group;" ::: "memory");
    };
    prefetch_gi(0, 0);
    __syncthreads();   // sW + sbh ready

    for (int t = 0; t < SS; t++) {
        if (t + 1 < SS) prefetch_gi(t + 1, (t + 1) & 1);
        const float* hprev = t ? (g_eo + (t - 1) * (HH * BB)) : g_h0;
        const float* hp = hprev + kq * 128 * 32 + lane;
        float s0 = 0, s1 = 0, s2 = 0;
        #pragma unroll 8
        for (int q = 0; q < 32; q++) {
            float h0 = hp[q * 128 + 0];
            float h1 = hp[q * 128 + 32];
            float h2 = hp[q * 128 + 64];
            float h3 = hp[q * 128 + 96];
            float4 w0 = *(const float4*)&sW[wid][0][q * 4];
            float4 w1 = *(const float4*)&sW[wid][1][q * 4];
            float4 w2 = *(const float4*)&sW[wid][2][q * 4];
            s0 += w0.x * h0 + w0.y * h1 + w0.z * h2 + w0.w * h3;
            s1 += w1.x * h0 + w1.y * h1 + w1.z * h2 + w1.w * h3;
            s2 += w2.x * h0 + w2.y * h1 + w2.z * h2 + w2.w * h3;
        }
        if (kq > 0) {
            ps[iLocal][kq - 1][0][lane] = s0;
            ps[iLocal][kq - 1][1][lane] = s1;
            ps[iLocal][kq - 1][2][lane] = s2;
        }
        asm volatile("cp.async.wait_group 1;" ::: "memory");
        __syncthreads();
        if (wid < 4) {
            float rh = s0 + ps[wid][0][0][lane] + ps[wid][1][0][lane] + ps[wid][2][0][lane] + sbh[wid];
            float zh = s1 + ps[wid][0][1][lane] + ps[wid][1][1][lane] + ps[wid][2][1][lane] + sbh[4 + wid];
            float nh = s2 + ps[wid][0][2][lane] + ps[wid][1][2][lane] + ps[wid][2][2][lane] + sbh[8 + wid];
            float ir = sgi[t & 1][wid][lane];
            float iz = sgi[t & 1][4 + wid][lane];
            float in_ = sgi[t & 1][8 + wid][lane];
            float r = sigm(ir + rh);
            float z = sigm(iz + zh);
            float n = tanhf(in_ + r * nh);
            int ii = blockIdx.x * 4 + wid;
            float hv = hprev[ii * 32 + lane];
            g_eo[t * (HH * BB) + ii * 32 + lane] = (1.0f - z) * n + z * hv;
        }
        grid_sync(gridDim.x);
    }
}

// ---------------- decoder scan (phase-D weights in dynamic SMEM, gie prefetched)
__global__ void __launch_bounds__(512) dec_scan(const float* __restrict__ Whh,
                                                const float* __restrict__ bhh,
                                                const float* __restrict__ Wih,
                                                const int* __restrict__ src) {
    extern __shared__ float sWD[];         // [wid][6][128] = 48KB
    int wid = threadIdx.x >> 5, lane = threadIdx.x & 31;
    int iLocal = wid & 3;
    int kqD = wid >> 2;
    int iD = blockIdx.x * 4 + iLocal;
    __shared__ float psA[2][8][32];
    __shared__ float psC[4][4][32];
    __shared__ float denS[32];
    __shared__ float psD[4][3][6][32];
    __shared__ float sgie[12][32];
    __shared__ float sbh[12];

    // one-time weight load: 6 matrices per warp (3 Whh rows, 3 Wih ctx rows)
    float* wrow = sWD + wid * 6 * 128;
    #pragma unroll
    for (int g = 0; g < 3; g++) {
        *(float4*)&wrow[g * 128 + lane * 4] =
            *(const float4*)(Whh + ((size_t)g * HH + iD) * HH + kqD * 128 + lane * 4);
        *(float4*)&wrow[(3 + g) * 128 + lane * 4] =
            *(const float4*)(Wih + ((size_t)g * HH + iD) * 768 + EE + kqD * 128 + lane * 4);
    }
    if (threadIdx.x < 12) {
        int g = threadIdx.x >> 2, il = threadIdx.x & 3;
        sbh[threadIdx.x] = bhh[g * HH + blockIdx.x * 4 + il];
    }
    __syncthreads();

    for (int t = 0; t < TT; t++) {
        // prefetch gie[t] (consumed in phase D of this step)
        if (threadIdx.x < 96) {
            int row = threadIdx.x >> 3, u = threadIdx.x & 7;
            int g = row >> 2, il = row & 3;
            const float* srcp = g_dec_gie + (size_t)t * (H3 * BB)
                              + ((size_t)g * HH + blockIdx.x * 4 + il) * 32 + u * 4;
            cpasync16(smem_u32(&sgie[row][u * 4]), srcp);
        }
        asm volatile("cp.async.commit_group;" ::: "memory");

        const float* h = t ? g_hdec[t & 1] : (g_eo + (SS - 1) * (HH * BB));
        {
            int s = blockIdx.x * 2 + (wid & 1);
            int kq8 = wid >> 1;
            float acc = 0.0f;
            const float* eo = g_eo + s * (HH * BB) + kq8 * 64 * 32 + lane;
            const float* hp = h + kq8 * 64 * 32 + lane;
            #pragma unroll 8
            for (int k = 0; k < 64; k++) acc += eo[k * 32] * hp[k * 32];
            psA[wid & 1][kq8][lane] = acc;
            __syncthreads();
            if (wid < 2) {
                int ss2 = blockIdx.x * 2 + wid;
                float sc = 0.0f;
                #pragma unroll
                for (int q = 0; q < 8; q++) sc += psA[wid][q][lane];
                int tokv = src[lane * SS + ss2];
                float e = (tokv == 0) ? 0.0f : __expf(sc);
                g_scores[ss2 * 32 + lane] = e;
            }
        }
        grid_sync(gridDim.x);
        {
            int k = blockIdx.x * 4 + (wid & 3);
            int sq = wid >> 2;
            float acc = 0.0f;
            const float* eo = g_eo + sq * 64 * (HH * BB) + k * 32 + lane;
            const float* sce = g_scores + sq * 64 * 32 + lane;
            #pragma unroll 8
            for (int s = 0; s < 64; s++) acc += sce[s * 32] * eo[s * (HH * BB)];
            psC[wid & 3][sq][lane] = acc;
            if (wid == 0) {
                float d = 0.0f;
                const float* sp = g_scores + lane;
                #pragma unroll 8
                for (int s = 0; s < SS; s++) d += sp[s * 32];
                denS[lane] = d;
            }
            __syncthreads();
            if (wid < 4) {
                int kk = blockIdx.x * 4 + wid;
                float c = (psC[wid][0][lane] + psC[wid][1][lane] + psC[wid][2][lane] + psC[wid][3][lane])
                          / denS[lane];
                g_ctx[kk * 32 + lane] = c;
                g_pred[(t * 32 + lane) * (2 * HH) + HH + kk] = c;
            }
        }
        grid_sync(gridDim.x);
        {
            float a0 = 0, a1 = 0, a2 = 0, c0 = 0, c1 = 0, c2 = 0;
            {
                const float* hp = h + kqD * 128 * 32 + lane;
                const float* cp = g_ctx + kqD * 128 * 32 + lane;
                #pragma unroll 4
                for (int q = 0; q < 32; q++) {
                    float h0 = hp[q * 128 + 0], h1 = hp[q * 128 + 32];
                    float h2 = hp[q * 128 + 64], h3 = hp[q * 128 + 96];
                    float x0 = cp[q * 128 + 0], x1 = cp[q * 128 + 32];
                    float x2 = cp[q * 128 + 64], x3 = cp[q * 128 + 96];
                    float4 w;
                    w = *(const float4*)&wrow[0 * 128 + q * 4];
                    a0 += w.x * h0 + w.y * h1 + w.z * h2 + w.w * h3;
                    w = *(const float4*)&wrow[1 * 128 + q * 4];
                    a1 += w.x * h0 + w.y * h1 + w.z * h2 + w.w * h3;
                    w = *(const float4*)&wrow[2 * 128 + q * 4];
                    a2 += w.x * h0 + w.y * h1 + w.z * h2 + w.w * h3;
                    w = *(const float4*)&wrow[3 * 128 + q * 4];
                    c0 += w.x * x0 + w.y * x1 + w.z * x2 + w.w * x3;
                    w = *(const float4*)&wrow[4 * 128 + q * 4];
                    c1 += w.x * x0 + w.y * x1 + w.z * x2 + w.w * x3;
                    w = *(const float4*)&wrow[5 * 128 + q * 4];
                    c2 += w.x * x0 + w.y * x1 + w.z * x2 + w.w * x3;
                }
            }
            if (kqD > 0) {
                psD[iLocal][kqD - 1][0][lane] = a0;
                psD[iLocal][kqD - 1][1][lane] = a1;
                psD[iLocal][kqD - 1][2][lane] = a2;
                psD[iLocal][kqD - 1][3][lane] = c0;
                psD[iLocal][kqD - 1][4][lane] = c1;
                psD[iLocal][kqD - 1][5][lane] = c2;
            }
            asm volatile("cp.async.wait_group 0;" ::: "memory");
            __syncthreads();
            if (wid < 4) {
                float rh = a0, zh = a1, nh = a2, rc = c0, zc = c1, nc = c2;
                #pragma unroll
                for (int kk = 0; kk < 3; kk++) {
                    rh += psD[wid][kk][0][lane];
                    zh += psD[wid][kk][1][lane];
                    nh += psD[wid][kk][2][lane];
                    rc += psD[wid][kk][3][lane];
                    zc += psD[wid][kk][4][lane];
                    nc += psD[wid][kk][5][lane];
                }
                rh += sbh[wid]; zh += sbh[4 + wid]; nh += sbh[8 + wid];
                float ir = sgie[wid][lane] + rc;
                float iz = sgie[4 + wid][lane] + zc;
                float in_ = sgie[8 + wid][lane] + nc;
                float r = sigm(ir + rh);
                float z = sigm(iz + zh);
                float n = tanhf(in_ + r * nh);
                int ii = blockIdx.x * 4 + wid;
                float hold = h[ii * 32 + lane];
                float hn = (1.0f - z) * n + z * hold;
                g_hdec[(t + 1) & 1][ii * 32 + lane] = hn;
                g_pred[(t * 32 + lane) * (2 * HH) + ii] = hn;
            }
        }
        grid_sync(gridDim.x);
    }
}

// ---------------- fc GEMM via mma.sync (256 thr, 128x128, K eff 3072) ----------
__global__ void __launch_bounds__(256) fc_mma(const float* __restrict__ bias,
                                              float* __restrict__ out) {
    extern __shared__ uint8_t dynsmem[];
    uint32_t sA = smem_u32(dynsmem);           // 3 stages
    uint32_t sB = sA + 3 * GBUF_B;

    int tid = threadIdx.x;
    int wid = tid >> 5, lane = tid & 31;
    int wm = wid & 3, wn = wid >> 2;
    int m0 = blockIdx.x * GBM;
    int n0 = blockIdx.y * GBN;

    const char* Ag = (const char*)(g_Ab + (size_t)m0 * FCK);
    const char* Bg = (const char*)(g_Wb + (size_t)n0 * FCK);
    int lrow = tid >> 3, lu = tid & 7;

    auto load_chunk = [&](int kc, int st) {
        int seg = kc >> 4, c = kc & 15;
        size_t aoff = (size_t)(((seg == 2) ? 1024 : 0) + c * 64) * 2;   // bytes
        size_t boff = (size_t)(((seg == 1) ? 1024 : 0) + c * 64) * 2;
        uint32_t sa = sA + st * GBUF_B;
        uint32_t sbm = sB + st * GBUF_B;
        #pragma unroll
        for (int it = 0; it < 4; it++) {
            int row = it * 32 + lrow;
            uint32_t doff = (uint32_t)(row * (GLDA * 2) + lu * 16);
            cpasync16(sa + doff, Ag + (size_t)row * (FCK * 2) + aoff + lu * 16);
            cpasync16(sbm + doff, Bg + (size_t)row * (FCK * 2) + boff + lu * 16);
        }
        asm volatile("cp.async.commit_group;" ::: "memory");
    };

    float acc[2][8][4];
    #pragma unroll
    for (int a = 0; a < 2; a++)
        #pragma unroll
        for (int b = 0; b < 8; b++)
            #pragma unroll
            for (int c = 0; c < 4; c++) acc[a][b][c] = 0.0f;

    uint32_t aBase = (uint32_t)(((wm * 32 + (lane & 15)) * GLDA + (lane >> 4) * 8) * 2);
    uint32_t bBase = (uint32_t)(((wn * 64 + (lane & 7) + ((lane >> 4) & 1) * 8) * GLDA
                                 + ((lane >> 3) & 1) * 8) * 2);

    load_chunk(0, 0);
    load_chunk(1, 1);
    for (int kc = 0; kc < FC_NC; kc++) {
        int st = kc % 3;
        if (kc == FC_NC - 1) { asm volatile("cp.async.wait_group 0;" ::: "memory"); }
        else                 { asm volatile("cp.async.wait_group 1;" ::: "memory"); }
        __syncthreads();
        if (kc + 2 < FC_NC) load_chunk(kc + 2, (kc + 2) % 3);
        uint32_t sa = sA + st * GBUF_B + aBase;
        uint32_t sbm = sB + st * GBUF_B + bBase;
        #pragma unroll
        for (int ks = 0; ks < 4; ks++) {
            uint32_t koff = (uint32_t)(ks * 16 * 2);
            uint32_t a0[4], a1[4];
            LDSM4(a0[0], a0[1], a0[2], a0[3], sa + koff);
            LDSM4(a1[0], a1[1], a1[2], a1[3], sa + 16 * GLDA * 2 + koff);
            uint32_t bf[16];
            #pragma unroll
            for (int nt = 0; nt < 4; nt++)
                LDSM4(bf[nt * 4 + 0], bf[nt * 4 + 1], bf[nt * 4 + 2], bf[nt * 4 + 3],
                      sbm + nt * 16 * GLDA * 2 + koff);
            #pragma unroll
            for (int j = 0; j < 8; j++) {
                int nt = j >> 1, hf = j & 1;
                MMA16816(acc[0][j], a0, bf[nt * 4 + hf * 2], bf[nt * 4 + hf * 2 + 1]);
                MMA16816(acc[1][j], a1, bf[nt * 4 + hf * 2], bf[nt * 4 + hf * 2 + 1]);
            }
        }
    }
    __syncthreads();

    float bv[8][2];
    #pragma unroll
    for (int j = 0; j < 8; j++) {
        int n = n0 + wn * 64 + j * 8 + (lane & 3) * 2;
        bv[j][0] = __ldg(bias + n);
        bv[j][1] = __ldg(bias + n + 1);
    }
    #pragma unroll
    for (int mt = 0; mt < 2; mt++) {
        #pragma unroll
        for (int half = 0; half < 2; half++) {
            int m = m0 + wm * 32 + mt * 16 + (lane >> 2) + half * 8;
            int t = m >> 5, b = m & 31;
            float* orow = out + (size_t)b * (TT * VV) + (size_t)t * VV;
            #pragma unroll
            for (int j = 0; j < 8; j++) {
                int n = n0 + wn * 64 + j * 8 + (lane & 3) * 2;
                float2 v;
                v.x = acc[mt][j][half * 2 + 0] + bv[j][0];
                v.y = acc[mt][j][half * 2 + 1] + bv[j][1];
                *(float2*)(orow + n) = v;
            }
        }
    }
}

// ---------------- launch ----------------
extern "C" void kernel_launch(void* const* d_in, const int* in_sizes, int n_in,
                              void* d_out, int out_size) {
    const int* src = (const int*)d_in[0];
    const int* tgt = (const int*)d_in[2];
    const float* enc_emb = (const float*)d_in[3];
    const float* enc_Wih = (const float*)d_in[4];
    const float* enc_Whh = (const float*)d_in[5];
    const float* enc_bih = (const float*)d_in[6];
    const float* enc_bhh = (const float*)d_in[7];
    const float* dec_emb = (const float*)d_in[8];
    const float* dec_Wih = (const float*)d_in[9];
    const float* dec_Whh = (const float*)d_in[10];
    const float* dec_bih = (const float*)d_in[11];
    const float* dec_bhh = (const float*)d_in[12];
    const float* fc_W = (const float*)d_in[13];
    const float* fc_b = (const float*)d_in[14];
    float* out = (float*)d_out;

    cudaFuncSetAttribute(fc_mma, cudaFuncAttributeMaxDynamicSharedMemorySize, MM_SMEM);
    cudaFuncSetAttribute(gi_mma, cudaFuncAttributeMaxDynamicSharedMemorySize, MM_SMEM);
    cudaFuncSetAttribute(dec_scan, cudaFuncAttributeMaxDynamicSharedMemorySize, DEC_WSMEM);

    gatherX<<<SS * BB / 8, 256>>>(enc_emb, src, SS, 0);                 // 1
    splitWih<<<H3 / 8, 256>>>(enc_Wih, EE, 0);                          // 2
    gi_mma<<<dim3(SS * BB / GBM, H3 / GBN), 256, MM_SMEM>>>(enc_bih, 0);// 3
    enc_scan<<<NCTA, 512>>>(enc_Whh, enc_bhh);                          // 4 <- profiled
    gatherX<<<TT * BB / 8, 256>>>(dec_emb, tgt, TT, 1);                 // 5
    splitWih<<<H3 / 8, 256>>>(dec_Wih, EE + HH, 1);                     // 6
    gi_mma<<<dim3(TT * BB / GBM, H3 / GBN), 256, MM_SMEM>>>(dec_bih, 1);// 7
    dec_scan<<<NCTA, 512, DEC_WSMEM>>>(dec_Whh, dec_bhh, dec_Wih, src); // 8
    convA<<<512, 1024>>>();                                             // 9
    convW<<<(VV * 256) / 1024, 1024>>>(fc_W);                           // 10
    fc_mma<<<dim3(TT * BB / GBM, VV / GBN), 256, MM_SMEM>>>(fc_b, out); // 11
}